// round 6
// baseline (speedup 1.0000x reference)
#include <cuda_runtime.h>
#include <cuda_bf16.h>
#include <cstdint>

#define Bsz 512
#define Tsz 256
#define Dsz 128
#define Hsz 512
#define GIN 768
#define TB  (Tsz*Bsz)          /* 131072 */
#define BH  (Bsz*Hsz)          /* 262144 */
#define NCTA 128

static const size_t TBH = (size_t)TB * Hsz;   /* 67108864 */

// loop-kernel smem layout (bytes)
#define OFF_WAH 0u
#define OFF_WAL 66560u
#define OFF_WBH 133120u
#define OFF_WBL 166400u
#define OFF_ACT_H 199680u
#define OFF_ACT_L 208896u
#define SMEM_TOTAL 218112

// precompute-gemm smem: 2 bufs x 4 tiles x (128 rows x 144B)
#define PG_TILE 18432u
#define PG_BUF  73728u
#define PG_SMEM 147456

// ---------------- scratch (__device__ globals: allocation-free) ----------------
__device__ float g_A [201326592];       // 3 x (T*B, H): affine terms (bias incl.)
__device__ float g_gh[67108864];        // (T*B, H): hidden decay gamma_h
__device__ float g_HD[BH];              // hd = gh*h (fp32)
__device__ float g_Z [BH];              // z gate
__device__ __nv_bfloat16 g_x1h[TB*256], g_x1l[TB*256];   // [xt|m] bf16 splits
__device__ __nv_bfloat16 g_dh [TB*128], g_dl [TB*128];   // delta bf16 splits
__device__ __nv_bfloat16 g_hd_hi[BH], g_hd_lo[BH];       // hd bf16 splits
__device__ __nv_bfloat16 g_rh_hi[BH], g_rh_lo[BH];       // r*hd bf16 splits
__device__ __nv_bfloat16 g_W_hi[3*Hsz*Hsz], g_W_lo[3*Hsz*Hsz];   // hidden slices
__device__ __nv_bfloat16 g_W1h[3*Hsz*256], g_W1l[3*Hsz*256];     // x|m slices
__device__ __nv_bfloat16 g_Wghh[Hsz*128], g_Wghl[Hsz*128];       // Wgh
__device__ unsigned g_bar[256];         // 8 group counters, 128B apart

// ---------------- small helpers ----------------
__device__ __forceinline__ float sigm(float x) { return 1.f / (1.f + expf(-x)); }
__device__ __forceinline__ uint32_t smem_u32(const void* p) {
    uint32_t a;
    asm("{ .reg .u64 t; cvta.to.shared.u64 t, %1; cvt.u32.u64 %0, t; }" : "=r"(a) : "l"(p));
    return a;
}
__device__ __forceinline__ void cpa16(uint32_t dst, const void* src) {
    asm volatile("cp.async.cg.shared.global [%0],[%1],16;" :: "r"(dst), "l"(src));
}
__device__ __forceinline__ void sts16(uint32_t a, uint4 v) {
    asm volatile("st.shared.v4.b32 [%0],{%1,%2,%3,%4};"
                 :: "r"(a), "r"(v.x), "r"(v.y), "r"(v.z), "r"(v.w));
}
__device__ __forceinline__ void ldsm4(uint32_t &r0, uint32_t &r1, uint32_t &r2,
                                      uint32_t &r3, uint32_t addr) {
    asm volatile("ldmatrix.sync.aligned.m8n8.x4.shared.b16 {%0,%1,%2,%3},[%4];"
                 : "=r"(r0), "=r"(r1), "=r"(r2), "=r"(r3) : "r"(addr));
}
__device__ __forceinline__ void mma_bf16(float* d, const uint32_t* a,
                                         uint32_t b0, uint32_t b1) {
    asm volatile("mma.sync.aligned.m16n8k16.row.col.f32.bf16.bf16.f32 "
                 "{%0,%1,%2,%3},{%4,%5,%6,%7},{%8,%9},{%0,%1,%2,%3};"
                 : "+f"(d[0]), "+f"(d[1]), "+f"(d[2]), "+f"(d[3])
                 : "r"(a[0]), "r"(a[1]), "r"(a[2]), "r"(a[3]), "r"(b0), "r"(b1));
}

// ---------------- group-local barrier (16 CTAs per row-group) -----------------
__device__ __forceinline__ void gsync_g(int grp, unsigned &target) {
    __syncthreads();
    __threadfence();
    if (threadIdx.x == 0) {
        unsigned* ctr = &g_bar[grp * 32];
        atomicAdd(ctr, 1u);
        while (*((volatile unsigned*)ctr) < target) { }
    }
    __syncthreads();
    target += 16;
}
__global__ void zero_bar_kernel() { g_bar[threadIdx.x] = 0u; }

// ---------------- P0: elementwise input-decay / staging (bf16 splits) ---------
__global__ void p0_kernel(const float* __restrict__ x,  const float* __restrict__ xl,
                          const float* __restrict__ mk, const float* __restrict__ dl,
                          const float* __restrict__ xmean,
                          const float* __restrict__ Wgx, const float* __restrict__ bgx) {
    int idx = blockIdx.x * 256 + threadIdx.x;
    int d   = idx & 127;
    int row = idx >> 7;
    int t   = row >> 9;
    int b   = row & 511;
    size_t xi = ((size_t)b * Tsz + t) * Dsz + d;
    float dv = dl[xi], mv = mk[xi];
    float gx = expf(-fmaxf(0.f, dv * Wgx[d * Dsz + d] + bgx[d]));
    float xt = mv * x[xi] + (1.f - mv) * (gx * xl[xi] + (1.f - gx) * xmean[d]);

    __nv_bfloat16 xh = __float2bfloat16(xt);
    g_x1h[(size_t)row * 256 + d] = xh;
    g_x1l[(size_t)row * 256 + d] = __float2bfloat16(xt - __bfloat162float(xh));
    g_x1h[(size_t)row * 256 + 128 + d] = __float2bfloat16(mv);   // exact (0/1)
    g_x1l[(size_t)row * 256 + 128 + d] = __float2bfloat16(0.f);
    __nv_bfloat16 dh = __float2bfloat16(dv);
    g_dh[(size_t)row * 128 + d] = dh;
    g_dl[(size_t)row * 128 + d] = __float2bfloat16(dv - __bfloat162float(dh));
}

// ---------------- prep: split weights into bf16 hi/lo -------------------------
__global__ void prep_w_kernel(const float* __restrict__ Wz, const float* __restrict__ Wr,
                              const float* __restrict__ Wn, const float* __restrict__ Wgh) {
    int idx = blockIdx.x * 256 + threadIdx.x;
    float w;
    __nv_bfloat16 *ph, *pl;
    if (idx < 786432) {                 // hidden slices: g*2^18 + j*512 + k
        int k = idx & 511, j = (idx >> 9) & 511, g = idx >> 18;
        const float* W = (g == 0) ? Wz : (g == 1) ? Wr : Wn;
        w = W[(size_t)j * GIN + 128 + k];
        ph = g_W_hi + idx; pl = g_W_lo + idx;
    } else if (idx < 786432 + 393216) { // x|m slices: g*(512*256) + j*256 + k
        int e = idx - 786432;
        int k = e & 255, j = (e >> 8) & 511, g = e >> 17;
        const float* W = (g == 0) ? Wz : (g == 1) ? Wr : Wn;
        int col = (k < 128) ? k : (512 + k);
        w = W[(size_t)j * GIN + col];
        ph = g_W1h + e; pl = g_W1l + e;
    } else if (idx < 786432 + 393216 + 65536) {
        int e = idx - 786432 - 393216;  // j*128 + k
        w = Wgh[e];
        ph = g_Wghh + e; pl = g_Wghl + e;
    } else return;
    __nv_bfloat16 hi = __float2bfloat16(w);
    *ph = hi;
    *pl = __float2bfloat16(w - __bfloat162float(hi));
}

// ---------------- precompute GEMM core (bf16x3, 128x128 tile, K chunks of 64) -
// term-major MMA order: hh pass, hl pass, lh pass -> no short RAW chains
template<int KCH>
__device__ __forceinline__ void pg_core(uint32_t sb,
        const __nv_bfloat16* __restrict__ Ah, const __nv_bfloat16* __restrict__ Al,
        const __nv_bfloat16* __restrict__ Bh, const __nv_bfloat16* __restrict__ Bl,
        int row0, int j0, int K, int tid, float d[2][8][4]) {
    #pragma unroll
    for (int mt = 0; mt < 2; mt++)
        #pragma unroll
        for (int nf = 0; nf < 8; nf++)
            #pragma unroll
            for (int i = 0; i < 4; i++) d[mt][nf][i] = 0.f;

    int wid = tid >> 5, l = tid & 31;
    int wr0 = (wid >> 1) * 32;
    int wn0 = (wid & 1) * 64;
    uint32_t aoff = (uint32_t)((wr0 + (l & 15)) * 144 + ((l >> 4) * 8) * 2);
    uint32_t boff = (uint32_t)((wn0 + ((l >> 4) << 3) + (l & 7)) * 144
                               + (((l >> 3) & 1) * 8) * 2);
    int sr = tid >> 3, ss = tid & 7;

    // prologue: chunk 0 -> buf0
    #pragma unroll
    for (int u = 0; u < 4; u++) {
        int r = sr + u * 32;
        uint32_t db = sb + (uint32_t)(r * 144 + ss * 16);
        cpa16(db,               Ah + (size_t)(row0 + r) * K + ss * 8);
        cpa16(db + PG_TILE,     Al + (size_t)(row0 + r) * K + ss * 8);
        cpa16(db + 2 * PG_TILE, Bh + (size_t)(j0 + r) * K + ss * 8);
        cpa16(db + 3 * PG_TILE, Bl + (size_t)(j0 + r) * K + ss * 8);
    }
    asm volatile("cp.async.commit_group;" ::: "memory");

    for (int c = 0; c < KCH; c++) {
        if (c + 1 < KCH) {
            uint32_t bb = sb + ((c + 1) & 1) * PG_BUF;
            #pragma unroll
            for (int u = 0; u < 4; u++) {
                int r = sr + u * 32;
                uint32_t db = bb + (uint32_t)(r * 144 + ss * 16);
                int ko = (c + 1) * 64 + ss * 8;
                cpa16(db,               Ah + (size_t)(row0 + r) * K + ko);
                cpa16(db + PG_TILE,     Al + (size_t)(row0 + r) * K + ko);
                cpa16(db + 2 * PG_TILE, Bh + (size_t)(j0 + r) * K + ko);
                cpa16(db + 3 * PG_TILE, Bl + (size_t)(j0 + r) * K + ko);
            }
            asm volatile("cp.async.commit_group;" ::: "memory");
            asm volatile("cp.async.wait_group 1;" ::: "memory");
        } else {
            asm volatile("cp.async.wait_group 0;" ::: "memory");
        }
        __syncthreads();
        uint32_t bb = sb + (c & 1) * PG_BUF;
        #pragma unroll
        for (int ks = 0; ks < 4; ks++) {
            uint32_t ko = (uint32_t)(ks * 32);
            uint32_t ah[2][4], al[2][4], bh[4][4], bl[4][4];
            #pragma unroll
            for (int mt = 0; mt < 2; mt++) {
                uint32_t a = bb + aoff + (uint32_t)(mt * 16 * 144) + ko;
                ldsm4(ah[mt][0], ah[mt][1], ah[mt][2], ah[mt][3], a);
                ldsm4(al[mt][0], al[mt][1], al[mt][2], al[mt][3], a + PG_TILE);
            }
            #pragma unroll
            for (int p = 0; p < 4; p++) {
                uint32_t b = bb + 2 * PG_TILE + boff + (uint32_t)(p * 16 * 144) + ko;
                ldsm4(bh[p][0], bh[p][1], bh[p][2], bh[p][3], b);
                ldsm4(bl[p][0], bl[p][1], bl[p][2], bl[p][3], b + PG_TILE);
            }
            #pragma unroll
            for (int p = 0; p < 4; p++)
                #pragma unroll
                for (int mt = 0; mt < 2; mt++) {
                    mma_bf16(d[mt][2*p],   ah[mt], bh[p][0], bh[p][1]);
                    mma_bf16(d[mt][2*p+1], ah[mt], bh[p][2], bh[p][3]);
                }
            #pragma unroll
            for (int p = 0; p < 4; p++)
                #pragma unroll
                for (int mt = 0; mt < 2; mt++) {
                    mma_bf16(d[mt][2*p],   ah[mt], bl[p][0], bl[p][1]);
                    mma_bf16(d[mt][2*p+1], ah[mt], bl[p][2], bl[p][3]);
                }
            #pragma unroll
            for (int p = 0; p < 4; p++)
                #pragma unroll
                for (int mt = 0; mt < 2; mt++) {
                    mma_bf16(d[mt][2*p],   al[mt], bh[p][0], bh[p][1]);
                    mma_bf16(d[mt][2*p+1], al[mt], bh[p][2], bh[p][3]);
                }
        }
        __syncthreads();
    }
}

// ---------------- P1 (MMA): A_s = [xt|m] @ W1_s^T + b_s -----------------------
// grid (12, 1024): x = s*4 + jtile (fast) so same-row CTAs share A in L2
__global__ __launch_bounds__(256, 1) void p1m_kernel(
        const float* __restrict__ bz, const float* __restrict__ br,
        const float* __restrict__ bn) {
    extern __shared__ char smem[];
    uint32_t sb = smem_u32(smem);
    int s = blockIdx.x >> 2, tid = threadIdx.x;
    int j0 = (blockIdx.x & 3) * 128, row0 = blockIdx.y * 128;
    const float* bias = (s == 0) ? bz : (s == 1) ? br : bn;
    float* out = g_A + (size_t)s * TBH;
    float d[2][8][4];
    pg_core<4>(sb, g_x1h, g_x1l,
               g_W1h + (size_t)s * Hsz * 256, g_W1l + (size_t)s * Hsz * 256,
               row0, j0, 256, tid, d);
    int wid = tid >> 5, l = tid & 31;
    int wr0 = (wid >> 1) * 32, wn0 = (wid & 1) * 64;
    #pragma unroll
    for (int mt = 0; mt < 2; mt++)
        #pragma unroll
        for (int nf = 0; nf < 8; nf++)
            #pragma unroll
            for (int h = 0; h < 2; h++) {
                int row = row0 + wr0 + mt * 16 + (l >> 2) + h * 8;
                int col = j0 + wn0 + nf * 8 + (l & 3) * 2;
                float2 v;
                v.x = d[mt][nf][h * 2]     + bias[col];
                v.y = d[mt][nf][h * 2 + 1] + bias[col + 1];
                *(float2*)(out + (size_t)row * Hsz + col) = v;
            }
}

// ---------------- P2 (MMA): gh = exp(-relu(delta @ Wgh^T + bgh)) --------------
__global__ __launch_bounds__(256, 1) void p2m_kernel(const float* __restrict__ bgh) {
    extern __shared__ char smem[];
    uint32_t sb = smem_u32(smem);
    int tid = threadIdx.x;
    int j0 = blockIdx.x * 128, row0 = blockIdx.y * 128;
    float d[2][8][4];
    pg_core<2>(sb, g_dh, g_dl, g_Wghh, g_Wghl, row0, j0, 128, tid, d);
    int wid = tid >> 5, l = tid & 31;
    int wr0 = (wid >> 1) * 32, wn0 = (wid & 1) * 64;
    #pragma unroll
    for (int mt = 0; mt < 2; mt++)
        #pragma unroll
        for (int nf = 0; nf < 8; nf++)
            #pragma unroll
            for (int h = 0; h < 2; h++) {
                int row = row0 + wr0 + mt * 16 + (l >> 2) + h * 8;
                int col = j0 + wn0 + nf * 8 + (l & 3) * 2;
                float2 v;
                v.x = expf(-fmaxf(0.f, d[mt][nf][h * 2]     + bgh[col]));
                v.y = expf(-fmaxf(0.f, d[mt][nf][h * 2 + 1] + bgh[col + 1]));
                *(float2*)(g_gh + (size_t)row * Hsz + col) = v;
            }
}

// ---------------- loop-kernel bf16x3 GEMM (term-major MMA order) --------------
template<int NF>
__device__ __forceinline__ void run_gemm(uint32_t sb, uint32_t wh, uint32_t wl,
        const __nv_bfloat16* __restrict__ gah, const __nv_bfloat16* __restrict__ gal,
        int r0, int tid, float (*d)[4]) {
    #pragma unroll
    for (int nf = 0; nf < NF; nf++)
        #pragma unroll
        for (int i = 0; i < 4; i++) d[nf][i] = 0.f;

    int wid = tid >> 5, l = tid & 31;
    int wr0 = (wid >> 1) * 16;
    int wn0 = (wid & 1) * (NF * 8);
    uint32_t Ah = sb + OFF_ACT_H, Al = sb + OFF_ACT_L;
    uint32_t aoff  = (uint32_t)((wr0 + (l & 15)) * 144 + ((l >> 4) * 8) * 2);
    uint32_t boff  = (uint32_t)((wn0 + ((l >> 4) << 3) + (l & 7)) * 1040
                                + (((l >> 3) & 1) * 8) * 2);
    uint32_t so0 = (uint32_t)((tid >> 3) * 144 + (tid & 7) * 16);
    uint32_t so1 = (uint32_t)(((tid + 256) >> 3) * 144 + (tid & 7) * 16);

    const __nv_bfloat16* sh0 = gah + (size_t)(r0 + (tid >> 3)) * Hsz + (tid & 7) * 8;
    const __nv_bfloat16* sh1 = gah + (size_t)(r0 + ((tid + 256) >> 3)) * Hsz + (tid & 7) * 8;
    const __nv_bfloat16* sl0 = gal + (size_t)(r0 + (tid >> 3)) * Hsz + (tid & 7) * 8;
    const __nv_bfloat16* sl1 = gal + (size_t)(r0 + ((tid + 256) >> 3)) * Hsz + (tid & 7) * 8;

    uint4 pf0 = __ldcg((const uint4*)sh0);
    uint4 pf1 = __ldcg((const uint4*)sh1);
    uint4 pf2 = __ldcg((const uint4*)sl0);
    uint4 pf3 = __ldcg((const uint4*)sl1);

    for (int c = 0; c < 8; c++) {
        sts16(Ah + so0, pf0); sts16(Ah + so1, pf1);
        sts16(Al + so0, pf2); sts16(Al + so1, pf3);
        __syncthreads();
        if (c < 7) {
            pf0 = __ldcg((const uint4*)(sh0 + (c + 1) * 64));
            pf1 = __ldcg((const uint4*)(sh1 + (c + 1) * 64));
            pf2 = __ldcg((const uint4*)(sl0 + (c + 1) * 64));
            pf3 = __ldcg((const uint4*)(sl1 + (c + 1) * 64));
        }
        #pragma unroll
        for (int ks = 0; ks < 4; ks++) {
            uint32_t ka = (uint32_t)(ks * 32);
            uint32_t kb = (uint32_t)((c * 64 + ks * 16) * 2);
            uint32_t ah[4], al[4], bh[NF/2][4], bl[NF/2][4];
            ldsm4(ah[0], ah[1], ah[2], ah[3], Ah + aoff + ka);
            ldsm4(al[0], al[1], al[2], al[3], Al + aoff + ka);
            #pragma unroll
            for (int g2 = 0; g2 < NF / 2; g2++) {
                uint32_t bo = boff + (uint32_t)(g2 * 16 * 1040) + kb;
                ldsm4(bh[g2][0], bh[g2][1], bh[g2][2], bh[g2][3], sb + wh + bo);
                ldsm4(bl[g2][0], bl[g2][1], bl[g2][2], bl[g2][3], sb + wl + bo);
            }
            #pragma unroll
            for (int g2 = 0; g2 < NF / 2; g2++) {
                mma_bf16(d[2*g2],     ah, bh[g2][0], bh[g2][1]);
                mma_bf16(d[2*g2 + 1], ah, bh[g2][2], bh[g2][3]);
            }
            #pragma unroll
            for (int g2 = 0; g2 < NF / 2; g2++) {
                mma_bf16(d[2*g2],     ah, bl[g2][0], bl[g2][1]);
                mma_bf16(d[2*g2 + 1], ah, bl[g2][2], bl[g2][3]);
            }
            #pragma unroll
            for (int g2 = 0; g2 < NF / 2; g2++) {
                mma_bf16(d[2*g2],     al, bh[g2][0], bh[g2][1]);
                mma_bf16(d[2*g2 + 1], al, bh[g2][2], bh[g2][3]);
            }
        }
        __syncthreads();
    }
}

// ---------------- persistent recurrent loop kernel ----------------------------
// 8 independent row-groups x 16 CTAs; group-local barriers.
__global__ __launch_bounds__(256, 1) void loop_kernel(float* __restrict__ out) {
    extern __shared__ char smem[];
    uint32_t sb = smem_u32(smem);
    int tid = threadIdx.x, cta = blockIdx.x;
    int wid = tid >> 5, l = tid & 31, g = l >> 2, tg = l & 3;

    int grp = cta >> 4, q = cta & 15;
    int sA  = q >> 3;                          // 0 = z, 1 = r
    int jA0 = (q & 7) * 64, rA0 = grp * 64;
    int jB0 = q * 32,       rB0 = grp * 64;
    const __nv_bfloat16* WAhi = g_W_hi + (size_t)sA * Hsz * Hsz;
    const __nv_bfloat16* WAlo = g_W_lo + (size_t)sA * Hsz * Hsz;
    const __nv_bfloat16* WBhi = g_W_hi + (size_t)2 * Hsz * Hsz;
    const __nv_bfloat16* WBlo = g_W_lo + (size_t)2 * Hsz * Hsz;

    for (int i = tid; i < 4096; i += 256) {
        int r = i >> 6, s = i & 63;
        uint32_t d0 = sb + OFF_WAH + r * 1040 + s * 16;
        cpa16(d0,                       WAhi + (size_t)(jA0 + r) * Hsz + s * 8);
        cpa16(d0 + (OFF_WAL - OFF_WAH), WAlo + (size_t)(jA0 + r) * Hsz + s * 8);
    }
    for (int i = tid; i < 2048; i += 256) {
        int r = i >> 6, s = i & 63;
        uint32_t d0 = sb + OFF_WBH + r * 1040 + s * 16;
        cpa16(d0,                       WBhi + (size_t)(jB0 + r) * Hsz + s * 8);
        cpa16(d0 + (OFF_WBL - OFF_WBH), WBlo + (size_t)(jB0 + r) * Hsz + s * 8);
    }
    asm volatile("cp.async.commit_group;" ::: "memory");
    asm volatile("cp.async.wait_group 0;" ::: "memory");

    // zero-init h-derived buffers (rows of this group only)
    __nv_bfloat16 zb = __float2bfloat16(0.f);
    for (int i = tid; i < 2048; i += 256) {
        int o = cta * 2048 + i;
        g_HD[o] = 0.f;
        g_hd_hi[o] = zb;
        g_hd_lo[o] = zb;
    }
    unsigned target = 16;
    gsync_g(grp, target);

    int wr0 = (wid >> 1) * 16;

    for (int t = 0; t < Tsz; t++) {
        {
            float d[4][4];
            run_gemm<4>(sb, OFF_WAH, OFF_WAL, g_hd_hi, g_hd_lo, rA0, tid, d);
            int wn0 = (wid & 1) * 32;
            const float* At = g_A + (size_t)sA * TBH + (size_t)t * BH;
            #pragma unroll
            for (int nf = 0; nf < 4; nf++) {
                int col = jA0 + wn0 + nf * 8 + tg * 2;
                #pragma unroll
                for (int h = 0; h < 2; h++) {
                    int row = rA0 + wr0 + g + h * 8;
                    size_t o = (size_t)row * Hsz + col;
                    float v0 = d[nf][h * 2], v1 = d[nf][h * 2 + 1];
                    float s0 = sigm(v0 + At[o]);
                    float s1 = sigm(v1 + At[o + 1]);
                    if (sA == 0) {
                        float2 zz = {s0, s1};
                        *(float2*)(g_Z + o) = zz;
                    } else {
                        float h0 = __ldcg(g_HD + o), h1 = __ldcg(g_HD + o + 1);
                        float r0v = s0 * h0, r1v = s1 * h1;
                        __nv_bfloat16 hh0 = __float2bfloat16(r0v);
                        __nv_bfloat16 hh1 = __float2bfloat16(r1v);
                        __nv_bfloat162 hp; hp.x = hh0; hp.y = hh1;
                        __nv_bfloat162 lp;
                        lp.x = __float2bfloat16(r0v - __bfloat162float(hh0));
                        lp.y = __float2bfloat16(r1v - __bfloat162float(hh1));
                        *(__nv_bfloat162*)(g_rh_hi + o) = hp;
                        *(__nv_bfloat162*)(g_rh_lo + o) = lp;
                    }
                }
            }
        }
        gsync_g(grp, target);

        {
            float d[2][4];
            run_gemm<2>(sb, OFF_WBH, OFF_WBL, g_rh_hi, g_rh_lo, rB0, tid, d);
            int wn0 = (wid & 1) * 16;
            const float* An = g_A + (size_t)2 * TBH + (size_t)t * BH;
            const float* ghn = g_gh + (size_t)(t + 1) * BH;
            bool last = (t == Tsz - 1);
            #pragma unroll
            for (int nf = 0; nf < 2; nf++) {
                int col = jB0 + wn0 + nf * 8 + tg * 2;
                #pragma unroll
                for (int h = 0; h < 2; h++) {
                    int row = rB0 + wr0 + g + h * 8;
                    size_t o = (size_t)row * Hsz + col;
                    #pragma unroll
                    for (int q2 = 0; q2 < 2; q2++) {
                        float ht = tanhf(d[nf][h * 2 + q2] + An[o + q2]);
                        float z  = __ldcg(g_Z + o + q2);
                        float hd = __ldcg(g_HD + o + q2);
                        float hp = (1.f - z) * hd + z * ht;
                        if (last) {
                            out[o + q2] = hp;
                        } else {
                            float hdn = ghn[o + q2] * hp;
                            g_HD[o + q2] = hdn;
                            __nv_bfloat16 hh = __float2bfloat16(hdn);
                            g_hd_hi[o + q2] = hh;
                            g_hd_lo[o + q2] = __float2bfloat16(hdn - __bfloat162float(hh));
                        }
                    }
                }
            }
        }
        gsync_g(grp, target);
    }
}

// ---------------- launch ----------------
extern "C" void kernel_launch(void* const* d_in, const int* in_sizes, int n_in,
                              void* d_out, int out_size) {
    const float* x    = (const float*)d_in[0];
    const float* xl   = (const float*)d_in[1];
    const float* mk   = (const float*)d_in[2];
    const float* dl   = (const float*)d_in[3];
    const float* xm   = (const float*)d_in[4];
    const float* Wz   = (const float*)d_in[5];
    const float* bz   = (const float*)d_in[6];
    const float* Wr   = (const float*)d_in[7];
    const float* br   = (const float*)d_in[8];
    const float* Wn   = (const float*)d_in[9];
    const float* bn   = (const float*)d_in[10];
    const float* Wgx  = (const float*)d_in[11];
    const float* bgx  = (const float*)d_in[12];
    const float* Wgh  = (const float*)d_in[13];
    const float* bgh  = (const float*)d_in[14];

    static int smem_set = 0;
    if (!smem_set) {
        cudaFuncSetAttribute(loop_kernel,
                             cudaFuncAttributeMaxDynamicSharedMemorySize, SMEM_TOTAL);
        cudaFuncSetAttribute(p1m_kernel,
                             cudaFuncAttributeMaxDynamicSharedMemorySize, PG_SMEM);
        cudaFuncSetAttribute(p2m_kernel,
                             cudaFuncAttributeMaxDynamicSharedMemorySize, PG_SMEM);
        smem_set = 1;
    }

    p0_kernel<<<(TB * Dsz) / 256, 256>>>(x, xl, mk, dl, xm, Wgx, bgx);
    prep_w_kernel<<<(786432 + 393216 + 65536) / 256, 256>>>(Wz, Wr, Wn, Wgh);
    p1m_kernel<<<dim3(12, 1024), 256, PG_SMEM>>>(bz, br, bn);
    p2m_kernel<<<dim3(4, 1024), 256, PG_SMEM>>>(bgh);
    zero_bar_kernel<<<1, 256>>>();
    loop_kernel<<<NCTA, 256, SMEM_TOTAL>>>((float*)d_out);
}

// round 7
// speedup vs baseline: 1.0919x; 1.0919x over previous
#include <cuda_runtime.h>
#include <cuda_bf16.h>
#include <cstdint>

#define Bsz 512
#define Tsz 256
#define Dsz 128
#define Hsz 512
#define GIN 768
#define TB  (Tsz*Bsz)          /* 131072 */
#define BH  (Bsz*Hsz)          /* 262144 */
#define NCTA 128

static const size_t TBH = (size_t)TB * Hsz;   /* 67108864 */

// loop-kernel smem layout (bytes)
#define OFF_WAH 0u
#define OFF_WAL 66560u
#define OFF_WBH 133120u
#define OFF_WBL 166400u
#define OFF_ACT_H 199680u
#define OFF_ACT_L 208896u
#define SMEM_TOTAL 218112

// precompute-gemm smem: 2 bufs x 4 tiles x (128 rows x 144B)
#define PG_TILE 18432u
#define PG_BUF  73728u
#define PG_SMEM 147456

// ---------------- scratch (__device__ globals: allocation-free) ----------------
__device__ float g_A [201326592];       // 3 x (T*B, H): affine terms (bias incl.)
__device__ float g_gh[67108864];        // (T*B, H): hidden decay gamma_h
__device__ float g_HD[BH];              // hd = gh*h (fp32)
__device__ float g_Z [BH];              // z gate
__device__ __nv_bfloat16 g_x1h[TB*256], g_x1l[TB*256];   // [xt|m] bf16 splits
__device__ __nv_bfloat16 g_dh [TB*128], g_dl [TB*128];   // delta bf16 splits
__device__ __nv_bfloat16 g_hd_hi[BH], g_hd_lo[BH];       // hd bf16 splits
__device__ __nv_bfloat16 g_rh_hi[BH], g_rh_lo[BH];       // r*hd bf16 splits
__device__ __nv_bfloat16 g_W_hi[3*Hsz*Hsz], g_W_lo[3*Hsz*Hsz];   // hidden slices
__device__ __nv_bfloat16 g_W1h[3*Hsz*256], g_W1l[3*Hsz*256];     // x|m slices
__device__ __nv_bfloat16 g_Wghh[Hsz*128], g_Wghl[Hsz*128];       // Wgh
__device__ unsigned g_bar[256];         // 8 group counters, 128B apart

// ---------------- small helpers ----------------
__device__ __forceinline__ float sigm(float x) { return 1.f / (1.f + expf(-x)); }
__device__ __forceinline__ uint32_t smem_u32(const void* p) {
    uint32_t a;
    asm("{ .reg .u64 t; cvta.to.shared.u64 t, %1; cvt.u32.u64 %0, t; }" : "=r"(a) : "l"(p));
    return a;
}
__device__ __forceinline__ void cpa16(uint32_t dst, const void* src) {
    asm volatile("cp.async.cg.shared.global [%0],[%1],16;" :: "r"(dst), "l"(src));
}
__device__ __forceinline__ void sts16(uint32_t a, uint4 v) {
    asm volatile("st.shared.v4.b32 [%0],{%1,%2,%3,%4};"
                 :: "r"(a), "r"(v.x), "r"(v.y), "r"(v.z), "r"(v.w));
}
__device__ __forceinline__ void ldsm4(uint32_t &r0, uint32_t &r1, uint32_t &r2,
                                      uint32_t &r3, uint32_t addr) {
    asm volatile("ldmatrix.sync.aligned.m8n8.x4.shared.b16 {%0,%1,%2,%3},[%4];"
                 : "=r"(r0), "=r"(r1), "=r"(r2), "=r"(r3) : "r"(addr));
}
__device__ __forceinline__ void mma_bf16(float* d, const uint32_t* a,
                                         uint32_t b0, uint32_t b1) {
    asm volatile("mma.sync.aligned.m16n8k16.row.col.f32.bf16.bf16.f32 "
                 "{%0,%1,%2,%3},{%4,%5,%6,%7},{%8,%9},{%0,%1,%2,%3};"
                 : "+f"(d[0]), "+f"(d[1]), "+f"(d[2]), "+f"(d[3])
                 : "r"(a[0]), "r"(a[1]), "r"(a[2]), "r"(a[3]), "r"(b0), "r"(b1));
}

// ---------------- group-local barrier (16 CTAs per row-group) -----------------
__device__ __forceinline__ void gsync_g(int grp, unsigned &target) {
    __syncthreads();
    __threadfence();
    if (threadIdx.x == 0) {
        unsigned* ctr = &g_bar[grp * 32];
        atomicAdd(ctr, 1u);
        while (*((volatile unsigned*)ctr) < target) { }
    }
    __syncthreads();
    target += 16;
}

// ---------------- K0: fused p0 (input decay staging) + weight split + bar -----
__global__ void p0prep_kernel(const float* __restrict__ x,  const float* __restrict__ xl,
                              const float* __restrict__ mk, const float* __restrict__ dl,
                              const float* __restrict__ xmean,
                              const float* __restrict__ Wgx, const float* __restrict__ bgx,
                              const float* __restrict__ Wz, const float* __restrict__ Wr,
                              const float* __restrict__ Wn, const float* __restrict__ Wgh) {
    int bx = blockIdx.x;
    if (bx < 65536) {
        int idx = bx * 256 + threadIdx.x;
        int d   = idx & 127;
        int row = idx >> 7;
        int t   = row >> 9;
        int b   = row & 511;
        size_t xi = ((size_t)b * Tsz + t) * Dsz + d;
        float dv = dl[xi], mv = mk[xi];
        float gx = expf(-fmaxf(0.f, dv * Wgx[d * Dsz + d] + bgx[d]));
        float xt = mv * x[xi] + (1.f - mv) * (gx * xl[xi] + (1.f - gx) * xmean[d]);
        __nv_bfloat16 xh = __float2bfloat16(xt);
        g_x1h[(size_t)row * 256 + d] = xh;
        g_x1l[(size_t)row * 256 + d] = __float2bfloat16(xt - __bfloat162float(xh));
        g_x1h[(size_t)row * 256 + 128 + d] = __float2bfloat16(mv);
        g_x1l[(size_t)row * 256 + 128 + d] = __float2bfloat16(0.f);
        __nv_bfloat16 dh = __float2bfloat16(dv);
        g_dh[(size_t)row * 128 + d] = dh;
        g_dl[(size_t)row * 128 + d] = __float2bfloat16(dv - __bfloat162float(dh));
    } else if (bx < 65536 + 4864) {
        int idx = (bx - 65536) * 256 + threadIdx.x;
        float w;
        __nv_bfloat16 *ph, *pl;
        if (idx < 786432) {                 // hidden slices: g*2^18 + j*512 + k
            int k = idx & 511, j = (idx >> 9) & 511, g = idx >> 18;
            const float* W = (g == 0) ? Wz : (g == 1) ? Wr : Wn;
            w = W[(size_t)j * GIN + 128 + k];
            ph = g_W_hi + idx; pl = g_W_lo + idx;
        } else if (idx < 786432 + 393216) { // x|m slices
            int e = idx - 786432;
            int k = e & 255, j = (e >> 8) & 511, g = e >> 17;
            const float* W = (g == 0) ? Wz : (g == 1) ? Wr : Wn;
            int col = (k < 128) ? k : (512 + k);
            w = W[(size_t)j * GIN + col];
            ph = g_W1h + e; pl = g_W1l + e;
        } else if (idx < 786432 + 393216 + 65536) {
            int e = idx - 786432 - 393216;
            w = Wgh[e];
            ph = g_Wghh + e; pl = g_Wghl + e;
        } else return;
        __nv_bfloat16 hi = __float2bfloat16(w);
        *ph = hi;
        *pl = __float2bfloat16(w - __bfloat162float(hi));
    } else {
        g_bar[threadIdx.x] = 0u;
    }
}

// ---------------- precompute GEMM core (bf16x3, 128x128 tile) -----------------
template<int KCH>
__device__ __forceinline__ void pg_core(uint32_t sb,
        const __nv_bfloat16* __restrict__ Ah, const __nv_bfloat16* __restrict__ Al,
        const __nv_bfloat16* __restrict__ Bh, const __nv_bfloat16* __restrict__ Bl,
        int row0, int j0, int K, int tid, float d[2][8][4]) {
    #pragma unroll
    for (int mt = 0; mt < 2; mt++)
        #pragma unroll
        for (int nf = 0; nf < 8; nf++)
            #pragma unroll
            for (int i = 0; i < 4; i++) d[mt][nf][i] = 0.f;

    int wid = tid >> 5, l = tid & 31;
    int wr0 = (wid >> 1) * 32;
    int wn0 = (wid & 1) * 64;
    uint32_t aoff = (uint32_t)((wr0 + (l & 15)) * 144 + ((l >> 4) * 8) * 2);
    uint32_t boff = (uint32_t)((wn0 + ((l >> 4) << 3) + (l & 7)) * 144
                               + (((l >> 3) & 1) * 8) * 2);
    int sr = tid >> 3, ss = tid & 7;

    #pragma unroll
    for (int u = 0; u < 4; u++) {
        int r = sr + u * 32;
        uint32_t db = sb + (uint32_t)(r * 144 + ss * 16);
        cpa16(db,               Ah + (size_t)(row0 + r) * K + ss * 8);
        cpa16(db + PG_TILE,     Al + (size_t)(row0 + r) * K + ss * 8);
        cpa16(db + 2 * PG_TILE, Bh + (size_t)(j0 + r) * K + ss * 8);
        cpa16(db + 3 * PG_TILE, Bl + (size_t)(j0 + r) * K + ss * 8);
    }
    asm volatile("cp.async.commit_group;" ::: "memory");

    for (int c = 0; c < KCH; c++) {
        if (c + 1 < KCH) {
            uint32_t bb = sb + ((c + 1) & 1) * PG_BUF;
            #pragma unroll
            for (int u = 0; u < 4; u++) {
                int r = sr + u * 32;
                uint32_t db = bb + (uint32_t)(r * 144 + ss * 16);
                int ko = (c + 1) * 64 + ss * 8;
                cpa16(db,               Ah + (size_t)(row0 + r) * K + ko);
                cpa16(db + PG_TILE,     Al + (size_t)(row0 + r) * K + ko);
                cpa16(db + 2 * PG_TILE, Bh + (size_t)(j0 + r) * K + ko);
                cpa16(db + 3 * PG_TILE, Bl + (size_t)(j0 + r) * K + ko);
            }
            asm volatile("cp.async.commit_group;" ::: "memory");
            asm volatile("cp.async.wait_group 1;" ::: "memory");
        } else {
            asm volatile("cp.async.wait_group 0;" ::: "memory");
        }
        __syncthreads();
        uint32_t bb = sb + (c & 1) * PG_BUF;
        #pragma unroll
        for (int ks = 0; ks < 4; ks++) {
            uint32_t ko = (uint32_t)(ks * 32);
            uint32_t ah[2][4], al[2][4], bh[4][4], bl[4][4];
            #pragma unroll
            for (int mt = 0; mt < 2; mt++) {
                uint32_t a = bb + aoff + (uint32_t)(mt * 16 * 144) + ko;
                ldsm4(ah[mt][0], ah[mt][1], ah[mt][2], ah[mt][3], a);
                ldsm4(al[mt][0], al[mt][1], al[mt][2], al[mt][3], a + PG_TILE);
            }
            #pragma unroll
            for (int p = 0; p < 4; p++) {
                uint32_t b = bb + 2 * PG_TILE + boff + (uint32_t)(p * 16 * 144) + ko;
                ldsm4(bh[p][0], bh[p][1], bh[p][2], bh[p][3], b);
                ldsm4(bl[p][0], bl[p][1], bl[p][2], bl[p][3], b + PG_TILE);
            }
            #pragma unroll
            for (int p = 0; p < 4; p++)
                #pragma unroll
                for (int mt = 0; mt < 2; mt++) {
                    mma_bf16(d[mt][2*p],   ah[mt], bh[p][0], bh[p][1]);
                    mma_bf16(d[mt][2*p+1], ah[mt], bh[p][2], bh[p][3]);
                }
            #pragma unroll
            for (int p = 0; p < 4; p++)
                #pragma unroll
                for (int mt = 0; mt < 2; mt++) {
                    mma_bf16(d[mt][2*p],   ah[mt], bl[p][0], bl[p][1]);
                    mma_bf16(d[mt][2*p+1], ah[mt], bl[p][2], bl[p][3]);
                }
            #pragma unroll
            for (int p = 0; p < 4; p++)
                #pragma unroll
                for (int mt = 0; mt < 2; mt++) {
                    mma_bf16(d[mt][2*p],   al[mt], bh[p][0], bh[p][1]);
                    mma_bf16(d[mt][2*p+1], al[mt], bh[p][2], bh[p][3]);
                }
        }
        __syncthreads();
    }
}

// ---------------- K1: fused p1m + p2m -----------------------------------------
__global__ __launch_bounds__(256, 1) void p12_kernel(
        const float* __restrict__ bz, const float* __restrict__ br,
        const float* __restrict__ bn, const float* __restrict__ bgh) {
    extern __shared__ char smem[];
    uint32_t sb = smem_u32(smem);
    int tid = threadIdx.x;
    int row0 = blockIdx.y * 128;
    int wid = tid >> 5, l = tid & 31;
    int wr0 = (wid >> 1) * 32, wn0 = (wid & 1) * 64;
    float d[2][8][4];
    if (blockIdx.x < 12) {
        int s = blockIdx.x >> 2;
        int j0 = (blockIdx.x & 3) * 128;
        const float* bias = (s == 0) ? bz : (s == 1) ? br : bn;
        float* out = g_A + (size_t)s * TBH;
        pg_core<4>(sb, g_x1h, g_x1l,
                   g_W1h + (size_t)s * Hsz * 256, g_W1l + (size_t)s * Hsz * 256,
                   row0, j0, 256, tid, d);
        #pragma unroll
        for (int mt = 0; mt < 2; mt++)
            #pragma unroll
            for (int nf = 0; nf < 8; nf++)
                #pragma unroll
                for (int h = 0; h < 2; h++) {
                    int row = row0 + wr0 + mt * 16 + (l >> 2) + h * 8;
                    int col = j0 + wn0 + nf * 8 + (l & 3) * 2;
                    float2 v;
                    v.x = d[mt][nf][h * 2]     + bias[col];
                    v.y = d[mt][nf][h * 2 + 1] + bias[col + 1];
                    *(float2*)(out + (size_t)row * Hsz + col) = v;
                }
    } else {
        int j0 = (blockIdx.x - 12) * 128;
        pg_core<2>(sb, g_dh, g_dl, g_Wghh, g_Wghl, row0, j0, 128, tid, d);
        #pragma unroll
        for (int mt = 0; mt < 2; mt++)
            #pragma unroll
            for (int nf = 0; nf < 8; nf++)
                #pragma unroll
                for (int h = 0; h < 2; h++) {
                    int row = row0 + wr0 + mt * 16 + (l >> 2) + h * 8;
                    int col = j0 + wn0 + nf * 8 + (l & 3) * 2;
                    float2 v;
                    v.x = expf(-fmaxf(0.f, d[mt][nf][h * 2]     + bgh[col]));
                    v.y = expf(-fmaxf(0.f, d[mt][nf][h * 2 + 1] + bgh[col + 1]));
                    *(float2*)(g_gh + (size_t)row * Hsz + col) = v;
                }
    }
}

__global__ void dummy_kernel() {}

// ---------------- loop-kernel bf16x3 GEMM, 512 threads ------------------------
// All warps stage; 'active' warps compute a 16x16 warp tile (d[2][4]).
__device__ __forceinline__ void run_gemm512(uint32_t sb, uint32_t wh, uint32_t wl,
        const __nv_bfloat16* __restrict__ gah, const __nv_bfloat16* __restrict__ gal,
        int r0, int tid, bool active, int wr0, int wn0, float (*d)[4]) {
    #pragma unroll
    for (int nf = 0; nf < 2; nf++)
        #pragma unroll
        for (int i = 0; i < 4; i++) d[nf][i] = 0.f;

    int l = tid & 31;
    uint32_t Ah = sb + OFF_ACT_H, Al = sb + OFF_ACT_L;
    uint32_t aoff = (uint32_t)((wr0 + (l & 15)) * 144 + ((l >> 4) * 8) * 2);
    uint32_t boff = (uint32_t)((wn0 + ((l >> 4) << 3) + (l & 7)) * 1040
                               + (((l >> 3) & 1) * 8) * 2);
    uint32_t so = (uint32_t)((tid >> 3) * 144 + (tid & 7) * 16);

    const __nv_bfloat16* ph = gah + (size_t)(r0 + (tid >> 3)) * Hsz + (tid & 7) * 8;
    const __nv_bfloat16* pl = gal + (size_t)(r0 + (tid >> 3)) * Hsz + (tid & 7) * 8;
    uint4 pf0 = __ldcg((const uint4*)ph);
    uint4 pf1 = __ldcg((const uint4*)pl);

    for (int c = 0; c < 8; c++) {
        sts16(Ah + so, pf0);
        sts16(Al + so, pf1);
        __syncthreads();
        if (c < 7) {
            pf0 = __ldcg((const uint4*)(ph + (c + 1) * 64));
            pf1 = __ldcg((const uint4*)(pl + (c + 1) * 64));
        }
        if (active) {
            #pragma unroll
            for (int ks = 0; ks < 4; ks++) {
                uint32_t ka = (uint32_t)(ks * 32);
                uint32_t kb = (uint32_t)((c * 64 + ks * 16) * 2);
                uint32_t ah[4], al[4], bh[4], bl[4];
                ldsm4(ah[0], ah[1], ah[2], ah[3], Ah + aoff + ka);
                ldsm4(al[0], al[1], al[2], al[3], Al + aoff + ka);
                ldsm4(bh[0], bh[1], bh[2], bh[3], sb + wh + boff + kb);
                ldsm4(bl[0], bl[1], bl[2], bl[3], sb + wl + boff + kb);
                mma_bf16(d[0], ah, bh[0], bh[1]);
                mma_bf16(d[1], ah, bh[2], bh[3]);
                mma_bf16(d[0], ah, bl[0], bl[1]);
                mma_bf16(d[1], ah, bl[2], bl[3]);
                mma_bf16(d[0], al, bh[0], bh[1]);
                mma_bf16(d[1], al, bh[2], bh[3]);
            }
        }
        __syncthreads();
    }
}

// ---------------- persistent recurrent loop kernel (512 threads) --------------
__global__ __launch_bounds__(512, 1) void loop_kernel(float* __restrict__ out) {
    extern __shared__ char smem[];
    uint32_t sb = smem_u32(smem);
    int tid = threadIdx.x, cta = blockIdx.x;
    int wid = tid >> 5, l = tid & 31;

    int grp = cta >> 4, q = cta & 15;
    int sA  = q >> 3;                          // 0 = z, 1 = r
    int jA0 = (q & 7) * 64, rA0 = grp * 64;
    int jB0 = q * 32,       rB0 = grp * 64;
    const __nv_bfloat16* WAhi = g_W_hi + (size_t)sA * Hsz * Hsz;
    const __nv_bfloat16* WAlo = g_W_lo + (size_t)sA * Hsz * Hsz;
    const __nv_bfloat16* WBhi = g_W_hi + (size_t)2 * Hsz * Hsz;
    const __nv_bfloat16* WBlo = g_W_lo + (size_t)2 * Hsz * Hsz;

    for (int i = tid; i < 4096; i += 512) {
        int r = i >> 6, s = i & 63;
        uint32_t d0 = sb + OFF_WAH + r * 1040 + s * 16;
        cpa16(d0,                       WAhi + (size_t)(jA0 + r) * Hsz + s * 8);
        cpa16(d0 + (OFF_WAL - OFF_WAH), WAlo + (size_t)(jA0 + r) * Hsz + s * 8);
    }
    for (int i = tid; i < 2048; i += 512) {
        int r = i >> 6, s = i & 63;
        uint32_t d0 = sb + OFF_WBH + r * 1040 + s * 16;
        cpa16(d0,                       WBhi + (size_t)(jB0 + r) * Hsz + s * 8);
        cpa16(d0 + (OFF_WBL - OFF_WBH), WBlo + (size_t)(jB0 + r) * Hsz + s * 8);
    }
    asm volatile("cp.async.commit_group;" ::: "memory");
    asm volatile("cp.async.wait_group 0;" ::: "memory");

    __nv_bfloat16 zb = __float2bfloat16(0.f);
    for (int i = tid; i < 2048; i += 512) {
        int o = cta * 2048 + i;
        g_HD[o] = 0.f;
        g_hd_hi[o] = zb;
        g_hd_lo[o] = zb;
    }
    unsigned target = 16;
    gsync_g(grp, target);

    // warp layouts
    int wr0A = (wid >> 2) * 16, wn0A = (wid & 3) * 16;     // 4x4 over 64x64
    bool actB = (wid < 8);
    int wr0B = (wid >> 1) * 16, wn0B = (wid & 1) * 16;     // 4x2 over 64x32

    for (int t = 0; t < Tsz; t++) {
        // ========== phase A: z (sA=0) or rh (sA=1) =============================
        {
            float d[2][4];
            run_gemm512(sb, OFF_WAH, OFF_WAL, g_hd_hi, g_hd_lo, rA0, tid,
                        true, wr0A, wn0A, d);
            const float* At = g_A + (size_t)sA * TBH + (size_t)t * BH;
            #pragma unroll
            for (int nf = 0; nf < 2; nf++) {
                int col = jA0 + wn0A + nf * 8 + (l & 3) * 2;
                #pragma unroll
                for (int h = 0; h < 2; h++) {
                    int row = rA0 + wr0A + (l >> 2) + h * 8;
                    size_t o = (size_t)row * Hsz + col;
                    float v0 = d[nf][h * 2], v1 = d[nf][h * 2 + 1];
                    float s0 = sigm(v0 + At[o]);
                    float s1 = sigm(v1 + At[o + 1]);
                    if (sA == 0) {
                        float2 zz = {s0, s1};
                        *(float2*)(g_Z + o) = zz;
                    } else {
                        float h0 = __ldcg(g_HD + o), h1 = __ldcg(g_HD + o + 1);
                        float r0v = s0 * h0, r1v = s1 * h1;
                        __nv_bfloat16 hh0 = __float2bfloat16(r0v);
                        __nv_bfloat16 hh1 = __float2bfloat16(r1v);
                        __nv_bfloat162 hp; hp.x = hh0; hp.y = hh1;
                        __nv_bfloat162 lp;
                        lp.x = __float2bfloat16(r0v - __bfloat162float(hh0));
                        lp.y = __float2bfloat16(r1v - __bfloat162float(hh1));
                        *(__nv_bfloat162*)(g_rh_hi + o) = hp;
                        *(__nv_bfloat162*)(g_rh_lo + o) = lp;
                    }
                }
            }
        }
        gsync_g(grp, target);

        // ========== phase B: h' = (1-z) hd + z tanh(An + rh Un^T) =============
        {
            float d[2][4];
            run_gemm512(sb, OFF_WBH, OFF_WBL, g_rh_hi, g_rh_lo, rB0, tid,
                        actB, wr0B, wn0B, d);
            if (actB) {
                const float* An = g_A + (size_t)2 * TBH + (size_t)t * BH;
                const float* ghn = g_gh + (size_t)(t + 1) * BH;
                bool last = (t == Tsz - 1);
                #pragma unroll
                for (int nf = 0; nf < 2; nf++) {
                    int col = jB0 + wn0B + nf * 8 + (l & 3) * 2;
                    #pragma unroll
                    for (int h = 0; h < 2; h++) {
                        int row = rB0 + wr0B + (l >> 2) + h * 8;
                        size_t o = (size_t)row * Hsz + col;
                        #pragma unroll
                        for (int q2 = 0; q2 < 2; q2++) {
                            float ht = tanhf(d[nf][h * 2 + q2] + An[o + q2]);
                            float z  = __ldcg(g_Z + o + q2);
                            float hd = __ldcg(g_HD + o + q2);
                            float hp = (1.f - z) * hd + z * ht;
                            if (last) {
                                out[o + q2] = hp;
                            } else {
                                float hdn = ghn[o + q2] * hp;
                                g_HD[o + q2] = hdn;
                                __nv_bfloat16 hh = __float2bfloat16(hdn);
                                g_hd_hi[o + q2] = hh;
                                g_hd_lo[o + q2] = __float2bfloat16(hdn - __bfloat162float(hh));
                            }
                        }
                    }
                }
            }
        }
        gsync_g(grp, target);
    }
}

// ---------------- launch ----------------
extern "C" void kernel_launch(void* const* d_in, const int* in_sizes, int n_in,
                              void* d_out, int out_size) {
    const float* x    = (const float*)d_in[0];
    const float* xl   = (const float*)d_in[1];
    const float* mk   = (const float*)d_in[2];
    const float* dl   = (const float*)d_in[3];
    const float* xm   = (const float*)d_in[4];
    const float* Wz   = (const float*)d_in[5];
    const float* bz   = (const float*)d_in[6];
    const float* Wr   = (const float*)d_in[7];
    const float* br   = (const float*)d_in[8];
    const float* Wn   = (const float*)d_in[9];
    const float* bn   = (const float*)d_in[10];
    const float* Wgx  = (const float*)d_in[11];
    const float* bgx  = (const float*)d_in[12];
    const float* Wgh  = (const float*)d_in[13];
    const float* bgh  = (const float*)d_in[14];

    static int smem_set = 0;
    if (!smem_set) {
        cudaFuncSetAttribute(loop_kernel,
                             cudaFuncAttributeMaxDynamicSharedMemorySize, SMEM_TOTAL);
        cudaFuncSetAttribute(p12_kernel,
                             cudaFuncAttributeMaxDynamicSharedMemorySize, PG_SMEM);
        smem_set = 1;
    }

    p0prep_kernel<<<65536 + 4864 + 1, 256>>>(x, xl, mk, dl, xm, Wgx, bgx,
                                             Wz, Wr, Wn, Wgh);
    p12_kernel<<<dim3(16, 1024), 256, PG_SMEM>>>(bz, br, bn, bgh);
    dummy_kernel<<<1, 32>>>();
    loop_kernel<<<NCTA, 512, SMEM_TOTAL>>>((float*)d_out);
}

// round 8
// speedup vs baseline: 1.3014x; 1.1919x over previous
#include <cuda_runtime.h>
#include <cuda_fp16.h>
#include <cstdint>

#define Bsz 512
#define Tsz 256
#define Dsz 128
#define Hsz 512
#define GIN 768
#define TB  (Tsz*Bsz)          /* 131072 */
#define BH  (Bsz*Hsz)          /* 262144 */
#define NCTA 128

static const size_t TBH = (size_t)TB * Hsz;   /* 67108864 */

// loop-kernel smem layout (bytes): weights hi/lo fp16 + single act buffer
#define OFF_WAH 0u
#define OFF_WAL 66560u
#define OFF_WBH 133120u
#define OFF_WBL 166400u
#define OFF_ACT 199680u
#define SMEM_TOTAL 217088      /* 199680 + 64*272 */

// precompute-gemm smem: 2 bufs x 3 tiles x (128 rows x 144B)
#define PG_TILE 18432u
#define PG_BUF  55296u
#define PG_SMEM 110592

// ---------------- scratch (__device__ globals: allocation-free) ----------------
__device__ float g_A [201326592];       // 3 x (T*B, H): affine terms (bias incl.)
__device__ float g_gh[67108864];        // (T*B, H): hidden decay gamma_h
__device__ float g_HD[BH];              // hd = gh*h (fp32)
__device__ float g_Z [BH];              // z gate
__device__ __half g_x1h[TB*256];        // [xt|m] fp16
__device__ __half g_dh [TB*128];        // delta fp16
__device__ __half g_hd_h[BH];           // hd fp16
__device__ __half g_rh_h[BH];           // r*hd fp16
__device__ __half g_Wh[3*Hsz*Hsz], g_Wl[3*Hsz*Hsz];     // hidden slices hi/lo
__device__ __half g_W1hh[3*Hsz*256], g_W1hl[3*Hsz*256]; // x|m slices hi/lo
__device__ __half g_Wghh[Hsz*128], g_Wghl[Hsz*128];     // Wgh hi/lo
__device__ unsigned g_bar[256];         // 8 group counters, 128B apart

// ---------------- small helpers ----------------
__device__ __forceinline__ float sigm(float x) { return 1.f / (1.f + expf(-x)); }
__device__ __forceinline__ uint32_t smem_u32(const void* p) {
    uint32_t a;
    asm("{ .reg .u64 t; cvta.to.shared.u64 t, %1; cvt.u32.u64 %0, t; }" : "=r"(a) : "l"(p));
    return a;
}
__device__ __forceinline__ void cpa16(uint32_t dst, const void* src) {
    asm volatile("cp.async.cg.shared.global [%0],[%1],16;" :: "r"(dst), "l"(src));
}
__device__ __forceinline__ void sts16(uint32_t a, uint4 v) {
    asm volatile("st.shared.v4.b32 [%0],{%1,%2,%3,%4};"
                 :: "r"(a), "r"(v.x), "r"(v.y), "r"(v.z), "r"(v.w));
}
__device__ __forceinline__ void ldsm4(uint32_t &r0, uint32_t &r1, uint32_t &r2,
                                      uint32_t &r3, uint32_t addr) {
    asm volatile("ldmatrix.sync.aligned.m8n8.x4.shared.b16 {%0,%1,%2,%3},[%4];"
                 : "=r"(r0), "=r"(r1), "=r"(r2), "=r"(r3) : "r"(addr));
}
__device__ __forceinline__ void mma_f16(float* d, const uint32_t* a,
                                        uint32_t b0, uint32_t b1) {
    asm volatile("mma.sync.aligned.m16n8k16.row.col.f32.f16.f16.f32 "
                 "{%0,%1,%2,%3},{%4,%5,%6,%7},{%8,%9},{%0,%1,%2,%3};"
                 : "+f"(d[0]), "+f"(d[1]), "+f"(d[2]), "+f"(d[3])
                 : "r"(a[0]), "r"(a[1]), "r"(a[2]), "r"(a[3]), "r"(b0), "r"(b1));
}

// ---------------- group-local barrier (16 CTAs per row-group) -----------------
__device__ __forceinline__ void gsync_g(int grp, unsigned &target) {
    __syncthreads();
    __threadfence();
    if (threadIdx.x == 0) {
        unsigned* ctr = &g_bar[grp * 32];
        atomicAdd(ctr, 1u);
        while (*((volatile unsigned*)ctr) < target) { }
    }
    __syncthreads();
    target += 16;
}

// ---------------- K0: fused p0 (input decay staging) + weight split + bar -----
__global__ void p0prep_kernel(const float* __restrict__ x,  const float* __restrict__ xl,
                              const float* __restrict__ mk, const float* __restrict__ dl,
                              const float* __restrict__ xmean,
                              const float* __restrict__ Wgx, const float* __restrict__ bgx,
                              const float* __restrict__ Wz, const float* __restrict__ Wr,
                              const float* __restrict__ Wn, const float* __restrict__ Wgh) {
    int bx = blockIdx.x;
    if (bx < 65536) {
        int idx = bx * 256 + threadIdx.x;
        int d   = idx & 127;
        int row = idx >> 7;
        int t   = row >> 9;
        int b   = row & 511;
        size_t xi = ((size_t)b * Tsz + t) * Dsz + d;
        float dv = dl[xi], mv = mk[xi];
        float gx = expf(-fmaxf(0.f, dv * Wgx[d * Dsz + d] + bgx[d]));
        float xt = mv * x[xi] + (1.f - mv) * (gx * xl[xi] + (1.f - gx) * xmean[d]);
        g_x1h[(size_t)row * 256 + d]       = __float2half(xt);
        g_x1h[(size_t)row * 256 + 128 + d] = __float2half(mv);
        g_dh [(size_t)row * 128 + d]       = __float2half(dv);
    } else if (bx < 65536 + 4864) {
        int idx = (bx - 65536) * 256 + threadIdx.x;
        float w;
        __half *ph, *pl;
        if (idx < 786432) {                 // hidden slices: g*2^18 + j*512 + k
            int k = idx & 511, j = (idx >> 9) & 511, g = idx >> 18;
            const float* W = (g == 0) ? Wz : (g == 1) ? Wr : Wn;
            w = W[(size_t)j * GIN + 128 + k];
            ph = g_Wh + idx; pl = g_Wl + idx;
        } else if (idx < 786432 + 393216) { // x|m slices
            int e = idx - 786432;
            int k = e & 255, j = (e >> 8) & 511, g = e >> 17;
            const float* W = (g == 0) ? Wz : (g == 1) ? Wr : Wn;
            int col = (k < 128) ? k : (512 + k);
            w = W[(size_t)j * GIN + col];
            ph = g_W1hh + e; pl = g_W1hl + e;
        } else if (idx < 786432 + 393216 + 65536) {
            int e = idx - 786432 - 393216;
            w = Wgh[e];
            ph = g_Wghh + e; pl = g_Wghl + e;
        } else return;
        __half hi = __float2half(w);
        *ph = hi;
        *pl = __float2half(w - __half2float(hi));
    } else {
        g_bar[threadIdx.x] = 0u;
    }
}

// ---------------- precompute GEMM core (fp16 2-term, 128x128 tile) ------------
// A = activations (hi only), B = weights (hi+lo). 64-col K chunks.
template<int KCH>
__device__ __forceinline__ void pg_core(uint32_t sb,
        const __half* __restrict__ Ah,
        const __half* __restrict__ Bh, const __half* __restrict__ Bl,
        int row0, int j0, int K, int tid, float d[2][8][4]) {
    #pragma unroll
    for (int mt = 0; mt < 2; mt++)
        #pragma unroll
        for (int nf = 0; nf < 8; nf++)
            #pragma unroll
            for (int i = 0; i < 4; i++) d[mt][nf][i] = 0.f;

    int wid = tid >> 5, l = tid & 31;
    int wr0 = (wid >> 1) * 32;
    int wn0 = (wid & 1) * 64;
    uint32_t aoff = (uint32_t)((wr0 + (l & 15)) * 144 + ((l >> 4) * 8) * 2);
    uint32_t boff = (uint32_t)((wn0 + ((l >> 4) << 3) + (l & 7)) * 144
                               + (((l >> 3) & 1) * 8) * 2);
    int sr = tid >> 3, ss = tid & 7;

    #pragma unroll
    for (int u = 0; u < 4; u++) {
        int r = sr + u * 32;
        uint32_t db = sb + (uint32_t)(r * 144 + ss * 16);
        cpa16(db,               Ah + (size_t)(row0 + r) * K + ss * 8);
        cpa16(db + PG_TILE,     Bh + (size_t)(j0 + r) * K + ss * 8);
        cpa16(db + 2 * PG_TILE, Bl + (size_t)(j0 + r) * K + ss * 8);
    }
    asm volatile("cp.async.commit_group;" ::: "memory");

    for (int c = 0; c < KCH; c++) {
        if (c + 1 < KCH) {
            uint32_t bb = sb + ((c + 1) & 1) * PG_BUF;
            #pragma unroll
            for (int u = 0; u < 4; u++) {
                int r = sr + u * 32;
                uint32_t db = bb + (uint32_t)(r * 144 + ss * 16);
                int ko = (c + 1) * 64 + ss * 8;
                cpa16(db,               Ah + (size_t)(row0 + r) * K + ko);
                cpa16(db + PG_TILE,     Bh + (size_t)(j0 + r) * K + ko);
                cpa16(db + 2 * PG_TILE, Bl + (size_t)(j0 + r) * K + ko);
            }
            asm volatile("cp.async.commit_group;" ::: "memory");
            asm volatile("cp.async.wait_group 1;" ::: "memory");
        } else {
            asm volatile("cp.async.wait_group 0;" ::: "memory");
        }
        __syncthreads();
        uint32_t bb = sb + (c & 1) * PG_BUF;
        #pragma unroll
        for (int ks = 0; ks < 4; ks++) {
            uint32_t ko = (uint32_t)(ks * 32);
            uint32_t ah[2][4], bh[4][4], bl[4][4];
            #pragma unroll
            for (int mt = 0; mt < 2; mt++) {
                uint32_t a = bb + aoff + (uint32_t)(mt * 16 * 144) + ko;
                ldsm4(ah[mt][0], ah[mt][1], ah[mt][2], ah[mt][3], a);
            }
            #pragma unroll
            for (int p = 0; p < 4; p++) {
                uint32_t b = bb + PG_TILE + boff + (uint32_t)(p * 16 * 144) + ko;
                ldsm4(bh[p][0], bh[p][1], bh[p][2], bh[p][3], b);
                ldsm4(bl[p][0], bl[p][1], bl[p][2], bl[p][3], b + PG_TILE);
            }
            #pragma unroll
            for (int p = 0; p < 4; p++)
                #pragma unroll
                for (int mt = 0; mt < 2; mt++) {
                    mma_f16(d[mt][2*p],   ah[mt], bh[p][0], bh[p][1]);
                    mma_f16(d[mt][2*p+1], ah[mt], bh[p][2], bh[p][3]);
                }
            #pragma unroll
            for (int p = 0; p < 4; p++)
                #pragma unroll
                for (int mt = 0; mt < 2; mt++) {
                    mma_f16(d[mt][2*p],   ah[mt], bl[p][0], bl[p][1]);
                    mma_f16(d[mt][2*p+1], ah[mt], bl[p][2], bl[p][3]);
                }
        }
        __syncthreads();
    }
}

// ---------------- K1: fused p1m + p2m -----------------------------------------
__global__ __launch_bounds__(256, 2) void p12_kernel(
        const float* __restrict__ bz, const float* __restrict__ br,
        const float* __restrict__ bn, const float* __restrict__ bgh) {
    extern __shared__ char smem[];
    uint32_t sb = smem_u32(smem);
    int tid = threadIdx.x;
    int row0 = blockIdx.y * 128;
    int wid = tid >> 5, l = tid & 31;
    int wr0 = (wid >> 1) * 32, wn0 = (wid & 1) * 64;
    float d[2][8][4];
    if (blockIdx.x < 12) {
        int s = blockIdx.x >> 2;
        int j0 = (blockIdx.x & 3) * 128;
        const float* bias = (s == 0) ? bz : (s == 1) ? br : bn;
        float* out = g_A + (size_t)s * TBH;
        pg_core<4>(sb, g_x1h,
                   g_W1hh + (size_t)s * Hsz * 256, g_W1hl + (size_t)s * Hsz * 256,
                   row0, j0, 256, tid, d);
        #pragma unroll
        for (int mt = 0; mt < 2; mt++)
            #pragma unroll
            for (int nf = 0; nf < 8; nf++)
                #pragma unroll
                for (int h = 0; h < 2; h++) {
                    int row = row0 + wr0 + mt * 16 + (l >> 2) + h * 8;
                    int col = j0 + wn0 + nf * 8 + (l & 3) * 2;
                    float2 v;
                    v.x = d[mt][nf][h * 2]     + bias[col];
                    v.y = d[mt][nf][h * 2 + 1] + bias[col + 1];
                    *(float2*)(out + (size_t)row * Hsz + col) = v;
                }
    } else {
        int j0 = (blockIdx.x - 12) * 128;
        pg_core<2>(sb, g_dh, g_Wghh, g_Wghl, row0, j0, 128, tid, d);
        #pragma unroll
        for (int mt = 0; mt < 2; mt++)
            #pragma unroll
            for (int nf = 0; nf < 8; nf++)
                #pragma unroll
                for (int h = 0; h < 2; h++) {
                    int row = row0 + wr0 + mt * 16 + (l >> 2) + h * 8;
                    int col = j0 + wn0 + nf * 8 + (l & 3) * 2;
                    float2 v;
                    v.x = expf(-fmaxf(0.f, d[mt][nf][h * 2]     + bgh[col]));
                    v.y = expf(-fmaxf(0.f, d[mt][nf][h * 2 + 1] + bgh[col + 1]));
                    *(float2*)(g_gh + (size_t)row * Hsz + col) = v;
                }
    }
}

__global__ void dummy_kernel() {}

// ---------------- loop-kernel fp16 2-term GEMM, 512 threads -------------------
// 4 K-chunks of 128 cols; act buffer: 64 rows x 272B (hi only).
__device__ __forceinline__ void run_gemm512(uint32_t sb, uint32_t wh, uint32_t wl,
        const __half* __restrict__ gah, int r0, int tid,
        bool active, int wr0, int wn0, float (*d)[4]) {
    #pragma unroll
    for (int nf = 0; nf < 2; nf++)
        #pragma unroll
        for (int i = 0; i < 4; i++) d[nf][i] = 0.f;

    int l = tid & 31;
    uint32_t A = sb + OFF_ACT;
    uint32_t aoff = (uint32_t)((wr0 + (l & 15)) * 272 + ((l >> 4) * 8) * 2);
    uint32_t boff = (uint32_t)((wn0 + ((l >> 4) << 3) + (l & 7)) * 1040
                               + (((l >> 3) & 1) * 8) * 2);
    // staging: 64 rows x 16 uint4 = 1024 uint4; 2 per thread
    int i0 = tid, i1 = tid + 512;
    int ra0 = i0 >> 4, ca0 = i0 & 15;
    int ra1 = i1 >> 4, ca1 = i1 & 15;
    uint32_t s0 = (uint32_t)(ra0 * 272 + ca0 * 16);
    uint32_t s1 = (uint32_t)(ra1 * 272 + ca1 * 16);
    const __half* p0 = gah + (size_t)(r0 + ra0) * Hsz + ca0 * 8;
    const __half* p1 = gah + (size_t)(r0 + ra1) * Hsz + ca1 * 8;
    uint4 pf0 = __ldcg((const uint4*)p0);
    uint4 pf1 = __ldcg((const uint4*)p1);

    for (int c = 0; c < 4; c++) {
        sts16(A + s0, pf0);
        sts16(A + s1, pf1);
        __syncthreads();
        if (c < 3) {
            pf0 = __ldcg((const uint4*)(p0 + (c + 1) * 128));
            pf1 = __ldcg((const uint4*)(p1 + (c + 1) * 128));
        }
        if (active) {
            #pragma unroll
            for (int ks = 0; ks < 8; ks++) {
                uint32_t ka = (uint32_t)(ks * 32);
                uint32_t kb = (uint32_t)((c * 128 + ks * 16) * 2);
                uint32_t ah[4], bh[4], bl[4];
                ldsm4(ah[0], ah[1], ah[2], ah[3], A + aoff + ka);
                ldsm4(bh[0], bh[1], bh[2], bh[3], sb + wh + boff + kb);
                ldsm4(bl[0], bl[1], bl[2], bl[3], sb + wl + boff + kb);
                mma_f16(d[0], ah, bh[0], bh[1]);
                mma_f16(d[1], ah, bh[2], bh[3]);
                mma_f16(d[0], ah, bl[0], bl[1]);
                mma_f16(d[1], ah, bl[2], bl[3]);
            }
        }
        __syncthreads();
    }
}

// ---------------- persistent recurrent loop kernel (512 threads) --------------
__global__ __launch_bounds__(512, 1) void loop_kernel(float* __restrict__ out) {
    extern __shared__ char smem[];
    uint32_t sb = smem_u32(smem);
    int tid = threadIdx.x, cta = blockIdx.x;
    int wid = tid >> 5, l = tid & 31;

    int grp = cta >> 4, q = cta & 15;
    int sA  = q >> 3;                          // 0 = z, 1 = r
    int jA0 = (q & 7) * 64, rA0 = grp * 64;
    int jB0 = q * 32,       rB0 = grp * 64;
    const __half* WAhi = g_Wh + (size_t)sA * Hsz * Hsz;
    const __half* WAlo = g_Wl + (size_t)sA * Hsz * Hsz;
    const __half* WBhi = g_Wh + (size_t)2 * Hsz * Hsz;
    const __half* WBlo = g_Wl + (size_t)2 * Hsz * Hsz;

    for (int i = tid; i < 4096; i += 512) {
        int r = i >> 6, s = i & 63;
        uint32_t d0 = sb + OFF_WAH + r * 1040 + s * 16;
        cpa16(d0,                       WAhi + (size_t)(jA0 + r) * Hsz + s * 8);
        cpa16(d0 + (OFF_WAL - OFF_WAH), WAlo + (size_t)(jA0 + r) * Hsz + s * 8);
    }
    for (int i = tid; i < 2048; i += 512) {
        int r = i >> 6, s = i & 63;
        uint32_t d0 = sb + OFF_WBH + r * 1040 + s * 16;
        cpa16(d0,                       WBhi + (size_t)(jB0 + r) * Hsz + s * 8);
        cpa16(d0 + (OFF_WBL - OFF_WBH), WBlo + (size_t)(jB0 + r) * Hsz + s * 8);
    }
    asm volatile("cp.async.commit_group;" ::: "memory");
    asm volatile("cp.async.wait_group 0;" ::: "memory");

    __half zh = __float2half(0.f);
    for (int i = tid; i < 2048; i += 512) {
        int o = cta * 2048 + i;
        g_HD[o] = 0.f;
        g_hd_h[o] = zh;
    }
    unsigned target = 16;
    gsync_g(grp, target);

    // warp layouts
    int wr0A = (wid >> 2) * 16, wn0A = (wid & 3) * 16;     // 4x4 over 64x64
    bool actB = (wid < 8);
    int wr0B = (wid >> 1) * 16, wn0B = (wid & 1) * 16;     // 4x2 over 64x32

    for (int t = 0; t < Tsz; t++) {
        // ========== phase A: z (sA=0) or rh (sA=1) =============================
        {
            float d[2][4];
            run_gemm512(sb, OFF_WAH, OFF_WAL, g_hd_h, rA0, tid,
                        true, wr0A, wn0A, d);
            const float* At = g_A + (size_t)sA * TBH + (size_t)t * BH;
            #pragma unroll
            for (int nf = 0; nf < 2; nf++) {
                int col = jA0 + wn0A + nf * 8 + (l & 3) * 2;
                #pragma unroll
                for (int h = 0; h < 2; h++) {
                    int row = rA0 + wr0A + (l >> 2) + h * 8;
                    size_t o = (size_t)row * Hsz + col;
                    float v0 = d[nf][h * 2], v1 = d[nf][h * 2 + 1];
                    float s0 = sigm(v0 + At[o]);
                    float s1 = sigm(v1 + At[o + 1]);
                    if (sA == 0) {
                        float2 zz = {s0, s1};
                        *(float2*)(g_Z + o) = zz;
                    } else {
                        float h0 = __ldcg(g_HD + o), h1 = __ldcg(g_HD + o + 1);
                        __half2 hp;
                        hp.x = __float2half(s0 * h0);
                        hp.y = __float2half(s1 * h1);
                        *(__half2*)(g_rh_h + o) = hp;
                    }
                }
            }
        }
        gsync_g(grp, target);

        // ========== phase B: h' = (1-z) hd + z tanh(An + rh Un^T) =============
        {
            float d[2][4];
            run_gemm512(sb, OFF_WBH, OFF_WBL, g_rh_h, rB0, tid,
                        actB, wr0B, wn0B, d);
            if (actB) {
                const float* An = g_A + (size_t)2 * TBH + (size_t)t * BH;
                const float* ghn = g_gh + (size_t)(t + 1) * BH;
                bool last = (t == Tsz - 1);
                #pragma unroll
                for (int nf = 0; nf < 2; nf++) {
                    int col = jB0 + wn0B + nf * 8 + (l & 3) * 2;
                    #pragma unroll
                    for (int h = 0; h < 2; h++) {
                        int row = rB0 + wr0B + (l >> 2) + h * 8;
                        size_t o = (size_t)row * Hsz + col;
                        #pragma unroll
                        for (int q2 = 0; q2 < 2; q2++) {
                            float ht = tanhf(d[nf][h * 2 + q2] + An[o + q2]);
                            float z  = __ldcg(g_Z + o + q2);
                            float hd = __ldcg(g_HD + o + q2);
                            float hp = (1.f - z) * hd + z * ht;
                            if (last) {
                                out[o + q2] = hp;
                            } else {
                                float hdn = ghn[o + q2] * hp;
                                g_HD[o + q2] = hdn;
                                g_hd_h[o + q2] = __float2half(hdn);
                            }
                        }
                    }
                }
            }
        }
        gsync_g(grp, target);
    }
}

// ---------------- launch ----------------
extern "C" void kernel_launch(void* const* d_in, const int* in_sizes, int n_in,
                              void* d_out, int out_size) {
    const float* x    = (const float*)d_in[0];
    const float* xl   = (const float*)d_in[1];
    const float* mk   = (const float*)d_in[2];
    const float* dl   = (const float*)d_in[3];
    const float* xm   = (const float*)d_in[4];
    const float* Wz   = (const float*)d_in[5];
    const float* bz   = (const float*)d_in[6];
    const float* Wr   = (const float*)d_in[7];
    const float* br   = (const float*)d_in[8];
    const float* Wn   = (const float*)d_in[9];
    const float* bn   = (const float*)d_in[10];
    const float* Wgx  = (const float*)d_in[11];
    const float* bgx  = (const float*)d_in[12];
    const float* Wgh  = (const float*)d_in[13];
    const float* bgh  = (const float*)d_in[14];

    static int smem_set = 0;
    if (!smem_set) {
        cudaFuncSetAttribute(loop_kernel,
                             cudaFuncAttributeMaxDynamicSharedMemorySize, SMEM_TOTAL);
        cudaFuncSetAttribute(p12_kernel,
                             cudaFuncAttributeMaxDynamicSharedMemorySize, PG_SMEM);
        smem_set = 1;
    }

    p0prep_kernel<<<65536 + 4864 + 1, 256>>>(x, xl, mk, dl, xm, Wgx, bgx,
                                             Wz, Wr, Wn, Wgh);
    p12_kernel<<<dim3(16, 1024), 256, PG_SMEM>>>(bz, br, bn, bgh);
    dummy_kernel<<<1, 32>>>();
    loop_kernel<<<NCTA, 512, SMEM_TOTAL>>>((float*)d_out);
}

// round 9
// speedup vs baseline: 1.5949x; 1.2255x over previous
#include <cuda_runtime.h>
#include <cuda_fp16.h>
#include <cstdint>

#define Bsz 512
#define Tsz 256
#define Dsz 128
#define Hsz 512
#define GIN 768
#define TB  (Tsz*Bsz)          /* 131072 */
#define BH  (Bsz*Hsz)          /* 262144 */
#define NCTA 128

static const size_t TBH = (size_t)TB * Hsz;   /* 67108864 */

// loop-kernel smem layout (bytes): hi-only fp16 weights + full act tile
#define OFF_WA  0u
#define OFF_WB  66560u
#define OFF_ACT 99840u
#define SMEM_TOTAL 166400

// precompute-gemm smem: 2 bufs x 3 tiles x (128 rows x 144B)
#define PG_TILE 18432u
#define PG_BUF  55296u
#define PG_SMEM 110592

// ---------------- scratch (__device__ globals: allocation-free) ----------------
__device__ float g_A [201326592];       // 3 x (T*B, H): affine terms (bias incl.)
__device__ float g_gh[67108864];        // (T*B, H): hidden decay gamma_h
__device__ float g_HD[BH];              // hd = gh*h (fp32)
__device__ float g_Z [BH];              // z gate
__device__ __half g_x1h[TB*256];        // [xt|m] fp16
__device__ __half g_dh [TB*128];        // delta fp16
__device__ __half g_hd_h[BH];           // hd fp16
__device__ __half g_rh_h[BH];           // r*hd fp16
__device__ __half g_Wh[3*Hsz*Hsz];      // hidden slices (hi only)
__device__ __half g_W1hh[3*Hsz*256], g_W1hl[3*Hsz*256]; // x|m slices hi/lo
__device__ __half g_Wghh[Hsz*128], g_Wghl[Hsz*128];     // Wgh hi/lo
__device__ unsigned g_bar[256];         // 8 group counters, 128B apart

// ---------------- small helpers ----------------
__device__ __forceinline__ float sigm(float x) { return 1.f / (1.f + expf(-x)); }
__device__ __forceinline__ uint32_t smem_u32(const void* p) {
    uint32_t a;
    asm("{ .reg .u64 t; cvta.to.shared.u64 t, %1; cvt.u32.u64 %0, t; }" : "=r"(a) : "l"(p));
    return a;
}
__device__ __forceinline__ void cpa16(uint32_t dst, const void* src) {
    asm volatile("cp.async.cg.shared.global [%0],[%1],16;" :: "r"(dst), "l"(src));
}
__device__ __forceinline__ void sts16(uint32_t a, uint4 v) {
    asm volatile("st.shared.v4.b32 [%0],{%1,%2,%3,%4};"
                 :: "r"(a), "r"(v.x), "r"(v.y), "r"(v.z), "r"(v.w));
}
__device__ __forceinline__ void ldsm4(uint32_t &r0, uint32_t &r1, uint32_t &r2,
                                      uint32_t &r3, uint32_t addr) {
    asm volatile("ldmatrix.sync.aligned.m8n8.x4.shared.b16 {%0,%1,%2,%3},[%4];"
                 : "=r"(r0), "=r"(r1), "=r"(r2), "=r"(r3) : "r"(addr));
}
__device__ __forceinline__ void mma_f16(float* d, const uint32_t* a,
                                        uint32_t b0, uint32_t b1) {
    asm volatile("mma.sync.aligned.m16n8k16.row.col.f32.f16.f16.f32 "
                 "{%0,%1,%2,%3},{%4,%5,%6,%7},{%8,%9},{%0,%1,%2,%3};"
                 : "+f"(d[0]), "+f"(d[1]), "+f"(d[2]), "+f"(d[3])
                 : "r"(a[0]), "r"(a[1]), "r"(a[2]), "r"(a[3]), "r"(b0), "r"(b1));
}

// ---------------- group-local barrier (16 CTAs per row-group) -----------------
__device__ __forceinline__ void gsync_g(int grp, unsigned &target) {
    __syncthreads();
    __threadfence();
    if (threadIdx.x == 0) {
        unsigned* ctr = &g_bar[grp * 32];
        atomicAdd(ctr, 1u);
        while (*((volatile unsigned*)ctr) < target) { }
    }
    __syncthreads();
    target += 16;
}

// ---------------- K0: fused p0 (input decay staging) + weight split + bar -----
__global__ void p0prep_kernel(const float* __restrict__ x,  const float* __restrict__ xl,
                              const float* __restrict__ mk, const float* __restrict__ dl,
                              const float* __restrict__ xmean,
                              const float* __restrict__ Wgx, const float* __restrict__ bgx,
                              const float* __restrict__ Wz, const float* __restrict__ Wr,
                              const float* __restrict__ Wn, const float* __restrict__ Wgh) {
    int bx = blockIdx.x;
    if (bx < 65536) {
        int idx = bx * 256 + threadIdx.x;
        int d   = idx & 127;
        int row = idx >> 7;
        int t   = row >> 9;
        int b   = row & 511;
        size_t xi = ((size_t)b * Tsz + t) * Dsz + d;
        float dv = dl[xi], mv = mk[xi];
        float gx = expf(-fmaxf(0.f, dv * Wgx[d * Dsz + d] + bgx[d]));
        float xt = mv * x[xi] + (1.f - mv) * (gx * xl[xi] + (1.f - gx) * xmean[d]);
        g_x1h[(size_t)row * 256 + d]       = __float2half(xt);
        g_x1h[(size_t)row * 256 + 128 + d] = __float2half(mv);
        g_dh [(size_t)row * 128 + d]       = __float2half(dv);
    } else if (bx < 65536 + 4864) {
        int idx = (bx - 65536) * 256 + threadIdx.x;
        if (idx < 786432) {                 // hidden slices (hi only)
            int k = idx & 511, j = (idx >> 9) & 511, g = idx >> 18;
            const float* W = (g == 0) ? Wz : (g == 1) ? Wr : Wn;
            g_Wh[idx] = __float2half(W[(size_t)j * GIN + 128 + k]);
        } else if (idx < 786432 + 393216) { // x|m slices hi/lo
            int e = idx - 786432;
            int k = e & 255, j = (e >> 8) & 511, g = e >> 17;
            const float* W = (g == 0) ? Wz : (g == 1) ? Wr : Wn;
            int col = (k < 128) ? k : (512 + k);
            float w = W[(size_t)j * GIN + col];
            __half hi = __float2half(w);
            g_W1hh[e] = hi;
            g_W1hl[e] = __float2half(w - __half2float(hi));
        } else if (idx < 786432 + 393216 + 65536) {
            int e = idx - 786432 - 393216;
            float w = Wgh[e];
            __half hi = __float2half(w);
            g_Wghh[e] = hi;
            g_Wghl[e] = __float2half(w - __half2float(hi));
        }
    } else {
        g_bar[threadIdx.x] = 0u;
    }
}

// ---------------- precompute GEMM core (fp16 2-term weights) ------------------
template<int KCH>
__device__ __forceinline__ void pg_core(uint32_t sb,
        const __half* __restrict__ Ah,
        const __half* __restrict__ Bh, const __half* __restrict__ Bl,
        int row0, int j0, int K, int tid, float d[2][8][4]) {
    #pragma unroll
    for (int mt = 0; mt < 2; mt++)
        #pragma unroll
        for (int nf = 0; nf < 8; nf++)
            #pragma unroll
            for (int i = 0; i < 4; i++) d[mt][nf][i] = 0.f;

    int wid = tid >> 5, l = tid & 31;
    int wr0 = (wid >> 1) * 32;
    int wn0 = (wid & 1) * 64;
    uint32_t aoff = (uint32_t)((wr0 + (l & 15)) * 144 + ((l >> 4) * 8) * 2);
    uint32_t boff = (uint32_t)((wn0 + ((l >> 4) << 3) + (l & 7)) * 144
                               + (((l >> 3) & 1) * 8) * 2);
    int sr = tid >> 3, ss = tid & 7;

    #pragma unroll
    for (int u = 0; u < 4; u++) {
        int r = sr + u * 32;
        uint32_t db = sb + (uint32_t)(r * 144 + ss * 16);
        cpa16(db,               Ah + (size_t)(row0 + r) * K + ss * 8);
        cpa16(db + PG_TILE,     Bh + (size_t)(j0 + r) * K + ss * 8);
        cpa16(db + 2 * PG_TILE, Bl + (size_t)(j0 + r) * K + ss * 8);
    }
    asm volatile("cp.async.commit_group;" ::: "memory");

    for (int c = 0; c < KCH; c++) {
        if (c + 1 < KCH) {
            uint32_t bb = sb + ((c + 1) & 1) * PG_BUF;
            #pragma unroll
            for (int u = 0; u < 4; u++) {
                int r = sr + u * 32;
                uint32_t db = bb + (uint32_t)(r * 144 + ss * 16);
                int ko = (c + 1) * 64 + ss * 8;
                cpa16(db,               Ah + (size_t)(row0 + r) * K + ko);
                cpa16(db + PG_TILE,     Bh + (size_t)(j0 + r) * K + ko);
                cpa16(db + 2 * PG_TILE, Bl + (size_t)(j0 + r) * K + ko);
            }
            asm volatile("cp.async.commit_group;" ::: "memory");
            asm volatile("cp.async.wait_group 1;" ::: "memory");
        } else {
            asm volatile("cp.async.wait_group 0;" ::: "memory");
        }
        __syncthreads();
        uint32_t bb = sb + (c & 1) * PG_BUF;
        #pragma unroll
        for (int ks = 0; ks < 4; ks++) {
            uint32_t ko = (uint32_t)(ks * 32);
            uint32_t ah[2][4], bh[4][4], bl[4][4];
            #pragma unroll
            for (int mt = 0; mt < 2; mt++) {
                uint32_t a = bb + aoff + (uint32_t)(mt * 16 * 144) + ko;
                ldsm4(ah[mt][0], ah[mt][1], ah[mt][2], ah[mt][3], a);
            }
            #pragma unroll
            for (int p = 0; p < 4; p++) {
                uint32_t b = bb + PG_TILE + boff + (uint32_t)(p * 16 * 144) + ko;
                ldsm4(bh[p][0], bh[p][1], bh[p][2], bh[p][3], b);
                ldsm4(bl[p][0], bl[p][1], bl[p][2], bl[p][3], b + PG_TILE);
            }
            #pragma unroll
            for (int p = 0; p < 4; p++)
                #pragma unroll
                for (int mt = 0; mt < 2; mt++) {
                    mma_f16(d[mt][2*p],   ah[mt], bh[p][0], bh[p][1]);
                    mma_f16(d[mt][2*p+1], ah[mt], bh[p][2], bh[p][3]);
                }
            #pragma unroll
            for (int p = 0; p < 4; p++)
                #pragma unroll
                for (int mt = 0; mt < 2; mt++) {
                    mma_f16(d[mt][2*p],   ah[mt], bl[p][0], bl[p][1]);
                    mma_f16(d[mt][2*p+1], ah[mt], bl[p][2], bl[p][3]);
                }
        }
        __syncthreads();
    }
}

// ---------------- K1: fused p1m + p2m -----------------------------------------
__global__ __launch_bounds__(256, 2) void p12_kernel(
        const float* __restrict__ bz, const float* __restrict__ br,
        const float* __restrict__ bn, const float* __restrict__ bgh) {
    extern __shared__ char smem[];
    uint32_t sb = smem_u32(smem);
    int tid = threadIdx.x;
    int row0 = blockIdx.y * 128;
    int wid = tid >> 5, l = tid & 31;
    int wr0 = (wid >> 1) * 32, wn0 = (wid & 1) * 64;
    float d[2][8][4];
    if (blockIdx.x < 12) {
        int s = blockIdx.x >> 2;
        int j0 = (blockIdx.x & 3) * 128;
        const float* bias = (s == 0) ? bz : (s == 1) ? br : bn;
        float* out = g_A + (size_t)s * TBH;
        pg_core<4>(sb, g_x1h,
                   g_W1hh + (size_t)s * Hsz * 256, g_W1hl + (size_t)s * Hsz * 256,
                   row0, j0, 256, tid, d);
        #pragma unroll
        for (int mt = 0; mt < 2; mt++)
            #pragma unroll
            for (int nf = 0; nf < 8; nf++)
                #pragma unroll
                for (int h = 0; h < 2; h++) {
                    int row = row0 + wr0 + mt * 16 + (l >> 2) + h * 8;
                    int col = j0 + wn0 + nf * 8 + (l & 3) * 2;
                    float2 v;
                    v.x = d[mt][nf][h * 2]     + bias[col];
                    v.y = d[mt][nf][h * 2 + 1] + bias[col + 1];
                    *(float2*)(out + (size_t)row * Hsz + col) = v;
                }
    } else {
        int j0 = (blockIdx.x - 12) * 128;
        pg_core<2>(sb, g_dh, g_Wghh, g_Wghl, row0, j0, 128, tid, d);
        #pragma unroll
        for (int mt = 0; mt < 2; mt++)
            #pragma unroll
            for (int nf = 0; nf < 8; nf++)
                #pragma unroll
                for (int h = 0; h < 2; h++) {
                    int row = row0 + wr0 + mt * 16 + (l >> 2) + h * 8;
                    int col = j0 + wn0 + nf * 8 + (l & 3) * 2;
                    float2 v;
                    v.x = expf(-fmaxf(0.f, d[mt][nf][h * 2]     + bgh[col]));
                    v.y = expf(-fmaxf(0.f, d[mt][nf][h * 2 + 1] + bgh[col + 1]));
                    *(float2*)(g_gh + (size_t)row * Hsz + col) = v;
                }
    }
}

__global__ void dummy_kernel() {}

// ---------------- loop helpers ------------------------------------------------
// stage full 64x512 fp16 act tile (66560B, stride 1040) in one shot
__device__ __forceinline__ void stage_act(uint32_t A, const __half* __restrict__ gact,
                                          int r0, int tid) {
    uint4 pf[8];
    #pragma unroll
    for (int u = 0; u < 8; u++) {
        int i = u * 512 + tid;
        pf[u] = __ldcg((const uint4*)(gact + (size_t)(r0 + (i >> 6)) * Hsz + (i & 63) * 8));
    }
    #pragma unroll
    for (int u = 0; u < 8; u++) {
        int i = u * 512 + tid;
        sts16(A + (uint32_t)((i >> 6) * 1040 + (i & 63) * 16), pf[u]);
    }
}

// 32-kstep fp16 GEMM over staged act (stride 1040) and smem weights (stride 1040)
__device__ __forceinline__ void mma_phase(uint32_t sb, uint32_t woff,
                                          int l, int wr0, int wn0, float (*d)[4]) {
    uint32_t Ab = sb + OFF_ACT;
    uint32_t aoff = (uint32_t)((wr0 + (l & 15)) * 1040 + ((l >> 4) * 8) * 2);
    uint32_t boff = (uint32_t)((wn0 + ((l >> 4) << 3) + (l & 7)) * 1040
                               + (((l >> 3) & 1) * 8) * 2);
    float dA0[4] = {0,0,0,0}, dA1[4] = {0,0,0,0};
    float dB0[4] = {0,0,0,0}, dB1[4] = {0,0,0,0};
    #pragma unroll
    for (int ks = 0; ks < 32; ks += 2) {
        uint32_t a0[4], b0[4], a1[4], b1[4];
        ldsm4(a0[0], a0[1], a0[2], a0[3], Ab + aoff + ks * 32);
        ldsm4(b0[0], b0[1], b0[2], b0[3], sb + woff + boff + ks * 32);
        ldsm4(a1[0], a1[1], a1[2], a1[3], Ab + aoff + ks * 32 + 32);
        ldsm4(b1[0], b1[1], b1[2], b1[3], sb + woff + boff + ks * 32 + 32);
        mma_f16(dA0, a0, b0[0], b0[1]);
        mma_f16(dA1, a0, b0[2], b0[3]);
        mma_f16(dB0, a1, b1[0], b1[1]);
        mma_f16(dB1, a1, b1[2], b1[3]);
    }
    #pragma unroll
    for (int i = 0; i < 4; i++) {
        d[0][i] = dA0[i] + dB0[i];
        d[1][i] = dA1[i] + dB1[i];
    }
}

// ---------------- persistent recurrent loop kernel (512 threads) --------------
__global__ __launch_bounds__(512, 1) void loop_kernel(float* __restrict__ out) {
    extern __shared__ char smem[];
    uint32_t sb = smem_u32(smem);
    int tid = threadIdx.x, cta = blockIdx.x;
    int wid = tid >> 5, l = tid & 31;

    int grp = cta >> 4, q = cta & 15;
    int sA  = q >> 3;                          // 0 = z, 1 = r
    int jA0 = (q & 7) * 64, rA0 = grp * 64;
    int jB0 = q * 32,       rB0 = grp * 64;
    const __half* WAhi = g_Wh + (size_t)sA * Hsz * Hsz;
    const __half* WBhi = g_Wh + (size_t)2 * Hsz * Hsz;

    // one-time: hi weights into smem (1040B row stride)
    for (int i = tid; i < 4096; i += 512) {
        int r = i >> 6, s = i & 63;
        cpa16(sb + OFF_WA + r * 1040 + s * 16, WAhi + (size_t)(jA0 + r) * Hsz + s * 8);
    }
    for (int i = tid; i < 2048; i += 512) {
        int r = i >> 6, s = i & 63;
        cpa16(sb + OFF_WB + r * 1040 + s * 16, WBhi + (size_t)(jB0 + r) * Hsz + s * 8);
    }
    asm volatile("cp.async.commit_group;" ::: "memory");
    asm volatile("cp.async.wait_group 0;" ::: "memory");

    __half zh = __float2half(0.f);
    for (int i = tid; i < 2048; i += 512) {
        int o = cta * 2048 + i;
        g_HD[o] = 0.f;
        g_hd_h[o] = zh;
    }
    unsigned target = 16;
    gsync_g(grp, target);

    // warp layouts
    int wr0A = (wid >> 2) * 16, wn0A = (wid & 3) * 16;     // 4x4 over 64x64
    bool actB = (wid < 8);
    int wr0B = (wid >> 1) * 16, wn0B = (wid & 1) * 16;     // 4x2 over 64x32

    for (int t = 0; t < Tsz; t++) {
        // ========== phase A: z (sA=0) or rh (sA=1) =============================
        {
            stage_act(sb + OFF_ACT, g_hd_h, rA0, tid);
            // prefetch epilogue operands (DRAM-streaming g_A; L2-hot g_HD)
            const float* At = g_A + (size_t)sA * TBH + (size_t)t * BH;
            float2 atv[4], hdv[4];
            #pragma unroll
            for (int nf = 0; nf < 2; nf++)
                #pragma unroll
                for (int h = 0; h < 2; h++) {
                    int col = jA0 + wn0A + nf * 8 + (l & 3) * 2;
                    int row = rA0 + wr0A + (l >> 2) + h * 8;
                    size_t o = (size_t)row * Hsz + col;
                    atv[nf * 2 + h] = __ldcg((const float2*)(At + o));
                    if (sA) hdv[nf * 2 + h] = __ldcg((const float2*)(g_HD + o));
                }
            __syncthreads();
            float d[2][4];
            mma_phase(sb, OFF_WA, l, wr0A, wn0A, d);
            #pragma unroll
            for (int nf = 0; nf < 2; nf++) {
                int col = jA0 + wn0A + nf * 8 + (l & 3) * 2;
                #pragma unroll
                for (int h = 0; h < 2; h++) {
                    int row = rA0 + wr0A + (l >> 2) + h * 8;
                    size_t o = (size_t)row * Hsz + col;
                    float2 a = atv[nf * 2 + h];
                    float s0 = sigm(d[nf][h * 2]     + a.x);
                    float s1 = sigm(d[nf][h * 2 + 1] + a.y);
                    if (sA == 0) {
                        float2 zz = {s0, s1};
                        *(float2*)(g_Z + o) = zz;
                    } else {
                        float2 hv = hdv[nf * 2 + h];
                        __half2 hp;
                        hp.x = __float2half(s0 * hv.x);
                        hp.y = __float2half(s1 * hv.y);
                        *(__half2*)(g_rh_h + o) = hp;
                    }
                }
            }
        }
        gsync_g(grp, target);

        // ========== phase B: h' = (1-z) hd + z tanh(An + rh Un^T) =============
        {
            stage_act(sb + OFF_ACT, g_rh_h, rB0, tid);
            const float* An = g_A + (size_t)2 * TBH + (size_t)t * BH;
            const float* ghn = g_gh + (size_t)(t + 1) * BH;
            bool last = (t == Tsz - 1);
            float2 anv[4], ghv[4];
            if (actB) {
                #pragma unroll
                for (int nf = 0; nf < 2; nf++)
                    #pragma unroll
                    for (int h = 0; h < 2; h++) {
                        int col = jB0 + wn0B + nf * 8 + (l & 3) * 2;
                        int row = rB0 + wr0B + (l >> 2) + h * 8;
                        size_t o = (size_t)row * Hsz + col;
                        anv[nf * 2 + h] = __ldcg((const float2*)(An + o));
                        if (!last) ghv[nf * 2 + h] = __ldcg((const float2*)(ghn + o));
                    }
            }
            __syncthreads();
            float d[2][4];
            if (actB) {
                mma_phase(sb, OFF_WB, l, wr0B, wn0B, d);
                #pragma unroll
                for (int nf = 0; nf < 2; nf++) {
                    int col = jB0 + wn0B + nf * 8 + (l & 3) * 2;
                    #pragma unroll
                    for (int h = 0; h < 2; h++) {
                        int row = rB0 + wr0B + (l >> 2) + h * 8;
                        size_t o = (size_t)row * Hsz + col;
                        float2 an = anv[nf * 2 + h];
                        float2 gv;
                        if (!last) gv = ghv[nf * 2 + h];
                        #pragma unroll
                        for (int q2 = 0; q2 < 2; q2++) {
                            float ht = tanhf(d[nf][h * 2 + q2] + (q2 ? an.y : an.x));
                            float z  = __ldcg(g_Z + o + q2);
                            float hd = __ldcg(g_HD + o + q2);
                            float hp = (1.f - z) * hd + z * ht;
                            if (last) {
                                out[o + q2] = hp;
                            } else {
                                float hdn = (q2 ? gv.y : gv.x) * hp;
                                g_HD[o + q2] = hdn;
                                g_hd_h[o + q2] = __float2half(hdn);
                            }
                        }
                    }
                }
            }
        }
        gsync_g(grp, target);
    }
}

// ---------------- launch ----------------
extern "C" void kernel_launch(void* const* d_in, const int* in_sizes, int n_in,
                              void* d_out, int out_size) {
    const float* x    = (const float*)d_in[0];
    const float* xl   = (const float*)d_in[1];
    const float* mk   = (const float*)d_in[2];
    const float* dl   = (const float*)d_in[3];
    const float* xm   = (const float*)d_in[4];
    const float* Wz   = (const float*)d_in[5];
    const float* bz   = (const float*)d_in[6];
    const float* Wr   = (const float*)d_in[7];
    const float* br   = (const float*)d_in[8];
    const float* Wn   = (const float*)d_in[9];
    const float* bn   = (const float*)d_in[10];
    const float* Wgx  = (const float*)d_in[11];
    const float* bgx  = (const float*)d_in[12];
    const float* Wgh  = (const float*)d_in[13];
    const float* bgh  = (const float*)d_in[14];

    static int smem_set = 0;
    if (!smem_set) {
        cudaFuncSetAttribute(loop_kernel,
                             cudaFuncAttributeMaxDynamicSharedMemorySize, SMEM_TOTAL);
        cudaFuncSetAttribute(p12_kernel,
                             cudaFuncAttributeMaxDynamicSharedMemorySize, PG_SMEM);
        smem_set = 1;
    }

    p0prep_kernel<<<65536 + 4864 + 1, 256>>>(x, xl, mk, dl, xm, Wgx, bgx,
                                             Wz, Wr, Wn, Wgh);
    p12_kernel<<<dim3(16, 1024), 256, PG_SMEM>>>(bz, br, bn, bgh);
    dummy_kernel<<<1, 32>>>();
    loop_kernel<<<NCTA, 512, SMEM_TOTAL>>>((float*)d_out);
}

// round 10
// speedup vs baseline: 1.7271x; 1.0829x over previous
#include <cuda_runtime.h>
#include <cuda_fp16.h>
#include <cstdint>

#define Bsz 512
#define Tsz 256
#define Dsz 128
#define Hsz 512
#define GIN 768
#define TB  (Tsz*Bsz)          /* 131072 */
#define BH  (Bsz*Hsz)          /* 262144 */
#define NCTA 128

static const size_t TBH = (size_t)TB * Hsz;   /* 67108864 */

// loop-kernel smem (bytes): WA 64x1040, WB 32x1040, ACT 32x1040, RED 4KB
#define OFF_WA  0u
#define OFF_WB  66560u
#define OFF_ACT 99840u
#define OFF_RED 133120u
#define SMEM_TOTAL 137216

// precompute-gemm smem: 2 bufs x 3 tiles x (128 rows x 144B)
#define PG_TILE 18432u
#define PG_BUF  55296u
#define PG_SMEM 110592

// ---------------- scratch (__device__ globals: allocation-free) ----------------
__device__ float g_A [201326592];       // 3 x (T*B, H): affine terms (bias incl.)
__device__ float g_gh[67108864];        // (T*B, H): hidden decay gamma_h
__device__ float g_HD[BH];              // hd = gh*h (fp32)
__device__ float g_Z [BH];              // z gate
__device__ __half g_x1h[TB*256];        // [xt|m] fp16
__device__ __half g_dh [TB*128];        // delta fp16
__device__ __half g_hd_h[BH];           // hd fp16
__device__ __half g_rh_h[BH];           // r*hd fp16
__device__ __half g_Wh[3*Hsz*Hsz];      // hidden slices (hi only)
__device__ __half g_W1hh[3*Hsz*256], g_W1hl[3*Hsz*256]; // x|m slices hi/lo
__device__ __half g_Wghh[Hsz*128], g_Wghl[Hsz*128];     // Wgh hi/lo
__device__ unsigned g_bar[512];         // 16 group counters, 128B apart

// ---------------- small helpers ----------------
__device__ __forceinline__ float sigm(float x) { return 1.f / (1.f + expf(-x)); }
__device__ __forceinline__ uint32_t smem_u32(const void* p) {
    uint32_t a;
    asm("{ .reg .u64 t; cvta.to.shared.u64 t, %1; cvt.u32.u64 %0, t; }" : "=r"(a) : "l"(p));
    return a;
}
__device__ __forceinline__ void cpa16(uint32_t dst, const void* src) {
    asm volatile("cp.async.cg.shared.global [%0],[%1],16;" :: "r"(dst), "l"(src));
}
__device__ __forceinline__ void sts16(uint32_t a, uint4 v) {
    asm volatile("st.shared.v4.b32 [%0],{%1,%2,%3,%4};"
                 :: "r"(a), "r"(v.x), "r"(v.y), "r"(v.z), "r"(v.w));
}
__device__ __forceinline__ void ldsm4(uint32_t &r0, uint32_t &r1, uint32_t &r2,
                                      uint32_t &r3, uint32_t addr) {
    asm volatile("ldmatrix.sync.aligned.m8n8.x4.shared.b16 {%0,%1,%2,%3},[%4];"
                 : "=r"(r0), "=r"(r1), "=r"(r2), "=r"(r3) : "r"(addr));
}
__device__ __forceinline__ void mma_f16(float* d, const uint32_t* a,
                                        uint32_t b0, uint32_t b1) {
    asm volatile("mma.sync.aligned.m16n8k16.row.col.f32.f16.f16.f32 "
                 "{%0,%1,%2,%3},{%4,%5,%6,%7},{%8,%9},{%0,%1,%2,%3};"
                 : "+f"(d[0]), "+f"(d[1]), "+f"(d[2]), "+f"(d[3])
                 : "r"(a[0]), "r"(a[1]), "r"(a[2]), "r"(a[3]), "r"(b0), "r"(b1));
}

// ---------------- group barrier primitives (16 CTAs per group) ----------------
__device__ __forceinline__ void arrive_g(int g) {
    __threadfence();
    __syncthreads();
    if (threadIdx.x == 0) atomicAdd(&g_bar[g * 32], 1u);
}
__device__ __forceinline__ void wait_g(int g, unsigned target) {
    if (threadIdx.x == 0) {
        while (*((volatile unsigned*)&g_bar[g * 32]) < target) { }
    }
    __syncthreads();
}

// ---------------- K0: fused p0 (input decay staging) + weight split + bar -----
__global__ void p0prep_kernel(const float* __restrict__ x,  const float* __restrict__ xl,
                              const float* __restrict__ mk, const float* __restrict__ dl,
                              const float* __restrict__ xmean,
                              const float* __restrict__ Wgx, const float* __restrict__ bgx,
                              const float* __restrict__ Wz, const float* __restrict__ Wr,
                              const float* __restrict__ Wn, const float* __restrict__ Wgh) {
    int bx = blockIdx.x;
    if (bx < 65536) {
        int idx = bx * 256 + threadIdx.x;
        int d   = idx & 127;
        int row = idx >> 7;
        int t   = row >> 9;
        int b   = row & 511;
        size_t xi = ((size_t)b * Tsz + t) * Dsz + d;
        float dv = dl[xi], mv = mk[xi];
        float gx = expf(-fmaxf(0.f, dv * Wgx[d * Dsz + d] + bgx[d]));
        float xt = mv * x[xi] + (1.f - mv) * (gx * xl[xi] + (1.f - gx) * xmean[d]);
        g_x1h[(size_t)row * 256 + d]       = __float2half(xt);
        g_x1h[(size_t)row * 256 + 128 + d] = __float2half(mv);
        g_dh [(size_t)row * 128 + d]       = __float2half(dv);
    } else if (bx < 65536 + 4864) {
        int idx = (bx - 65536) * 256 + threadIdx.x;
        if (idx < 786432) {                 // hidden slices (hi only)
            int k = idx & 511, j = (idx >> 9) & 511, g = idx >> 18;
            const float* W = (g == 0) ? Wz : (g == 1) ? Wr : Wn;
            g_Wh[idx] = __float2half(W[(size_t)j * GIN + 128 + k]);
        } else if (idx < 786432 + 393216) { // x|m slices hi/lo
            int e = idx - 786432;
            int k = e & 255, j = (e >> 8) & 511, g = e >> 17;
            const float* W = (g == 0) ? Wz : (g == 1) ? Wr : Wn;
            int col = (k < 128) ? k : (512 + k);
            float w = W[(size_t)j * GIN + col];
            __half hi = __float2half(w);
            g_W1hh[e] = hi;
            g_W1hl[e] = __float2half(w - __half2float(hi));
        } else if (idx < 786432 + 393216 + 65536) {
            int e = idx - 786432 - 393216;
            float w = Wgh[e];
            __half hi = __float2half(w);
            g_Wghh[e] = hi;
            g_Wghl[e] = __float2half(w - __half2float(hi));
        }
    } else {
        g_bar[threadIdx.x] = 0u;
        g_bar[threadIdx.x + 256] = 0u;
    }
}

// ---------------- precompute GEMM core (fp16 2-term weights) ------------------
template<int KCH>
__device__ __forceinline__ void pg_core(uint32_t sb,
        const __half* __restrict__ Ah,
        const __half* __restrict__ Bh, const __half* __restrict__ Bl,
        int row0, int j0, int K, int tid, float d[2][8][4]) {
    #pragma unroll
    for (int mt = 0; mt < 2; mt++)
        #pragma unroll
        for (int nf = 0; nf < 8; nf++)
            #pragma unroll
            for (int i = 0; i < 4; i++) d[mt][nf][i] = 0.f;

    int wid = tid >> 5, l = tid & 31;
    int wr0 = (wid >> 1) * 32;
    int wn0 = (wid & 1) * 64;
    uint32_t aoff = (uint32_t)((wr0 + (l & 15)) * 144 + ((l >> 4) * 8) * 2);
    uint32_t boff = (uint32_t)((wn0 + ((l >> 4) << 3) + (l & 7)) * 144
                               + (((l >> 3) & 1) * 8) * 2);
    int sr = tid >> 3, ss = tid & 7;

    #pragma unroll
    for (int u = 0; u < 4; u++) {
        int r = sr + u * 32;
        uint32_t db = sb + (uint32_t)(r * 144 + ss * 16);
        cpa16(db,               Ah + (size_t)(row0 + r) * K + ss * 8);
        cpa16(db + PG_TILE,     Bh + (size_t)(j0 + r) * K + ss * 8);
        cpa16(db + 2 * PG_TILE, Bl + (size_t)(j0 + r) * K + ss * 8);
    }
    asm volatile("cp.async.commit_group;" ::: "memory");

    for (int c = 0; c < KCH; c++) {
        if (c + 1 < KCH) {
            uint32_t bb = sb + ((c + 1) & 1) * PG_BUF;
            #pragma unroll
            for (int u = 0; u < 4; u++) {
                int r = sr + u * 32;
                uint32_t db = bb + (uint32_t)(r * 144 + ss * 16);
                int ko = (c + 1) * 64 + ss * 8;
                cpa16(db,               Ah + (size_t)(row0 + r) * K + ko);
                cpa16(db + PG_TILE,     Bh + (size_t)(j0 + r) * K + ko);
                cpa16(db + 2 * PG_TILE, Bl + (size_t)(j0 + r) * K + ko);
            }
            asm volatile("cp.async.commit_group;" ::: "memory");
            asm volatile("cp.async.wait_group 1;" ::: "memory");
        } else {
            asm volatile("cp.async.wait_group 0;" ::: "memory");
        }
        __syncthreads();
        uint32_t bb = sb + (c & 1) * PG_BUF;
        #pragma unroll
        for (int ks = 0; ks < 4; ks++) {
            uint32_t ko = (uint32_t)(ks * 32);
            uint32_t ah[2][4], bh[4][4], bl[4][4];
            #pragma unroll
            for (int mt = 0; mt < 2; mt++) {
                uint32_t a = bb + aoff + (uint32_t)(mt * 16 * 144) + ko;
                ldsm4(ah[mt][0], ah[mt][1], ah[mt][2], ah[mt][3], a);
            }
            #pragma unroll
            for (int p = 0; p < 4; p++) {
                uint32_t b = bb + PG_TILE + boff + (uint32_t)(p * 16 * 144) + ko;
                ldsm4(bh[p][0], bh[p][1], bh[p][2], bh[p][3], b);
                ldsm4(bl[p][0], bl[p][1], bl[p][2], bl[p][3], b + PG_TILE);
            }
            #pragma unroll
            for (int p = 0; p < 4; p++)
                #pragma unroll
                for (int mt = 0; mt < 2; mt++) {
                    mma_f16(d[mt][2*p],   ah[mt], bh[p][0], bh[p][1]);
                    mma_f16(d[mt][2*p+1], ah[mt], bh[p][2], bh[p][3]);
                }
            #pragma unroll
            for (int p = 0; p < 4; p++)
                #pragma unroll
                for (int mt = 0; mt < 2; mt++) {
                    mma_f16(d[mt][2*p],   ah[mt], bl[p][0], bl[p][1]);
                    mma_f16(d[mt][2*p+1], ah[mt], bl[p][2], bl[p][3]);
                }
        }
        __syncthreads();
    }
}

// ---------------- K1: fused p1m + p2m -----------------------------------------
__global__ __launch_bounds__(256, 2) void p12_kernel(
        const float* __restrict__ bz, const float* __restrict__ br,
        const float* __restrict__ bn, const float* __restrict__ bgh) {
    extern __shared__ char smem[];
    uint32_t sb = smem_u32(smem);
    int tid = threadIdx.x;
    int row0 = blockIdx.y * 128;
    int wid = tid >> 5, l = tid & 31;
    int wr0 = (wid >> 1) * 32, wn0 = (wid & 1) * 64;
    float d[2][8][4];
    if (blockIdx.x < 12) {
        int s = blockIdx.x >> 2;
        int j0 = (blockIdx.x & 3) * 128;
        const float* bias = (s == 0) ? bz : (s == 1) ? br : bn;
        float* out = g_A + (size_t)s * TBH;
        pg_core<4>(sb, g_x1h,
                   g_W1hh + (size_t)s * Hsz * 256, g_W1hl + (size_t)s * Hsz * 256,
                   row0, j0, 256, tid, d);
        #pragma unroll
        for (int mt = 0; mt < 2; mt++)
            #pragma unroll
            for (int nf = 0; nf < 8; nf++)
                #pragma unroll
                for (int h = 0; h < 2; h++) {
                    int row = row0 + wr0 + mt * 16 + (l >> 2) + h * 8;
                    int col = j0 + wn0 + nf * 8 + (l & 3) * 2;
                    float2 v;
                    v.x = d[mt][nf][h * 2]     + bias[col];
                    v.y = d[mt][nf][h * 2 + 1] + bias[col + 1];
                    *(float2*)(out + (size_t)row * Hsz + col) = v;
                }
    } else {
        int j0 = (blockIdx.x - 12) * 128;
        pg_core<2>(sb, g_dh, g_Wghh, g_Wghl, row0, j0, 128, tid, d);
        #pragma unroll
        for (int mt = 0; mt < 2; mt++)
            #pragma unroll
            for (int nf = 0; nf < 8; nf++)
                #pragma unroll
                for (int h = 0; h < 2; h++) {
                    int row = row0 + wr0 + mt * 16 + (l >> 2) + h * 8;
                    int col = j0 + wn0 + nf * 8 + (l & 3) * 2;
                    float2 v;
                    v.x = expf(-fmaxf(0.f, d[mt][nf][h * 2]     + bgh[col]));
                    v.y = expf(-fmaxf(0.f, d[mt][nf][h * 2 + 1] + bgh[col + 1]));
                    *(float2*)(g_gh + (size_t)row * Hsz + col) = v;
                }
    }
}

__global__ void dummy_kernel() {}

// ---------------- loop helpers ------------------------------------------------
// stage 32x512 fp16 act tile (rows r0..r0+31) into smem (stride 1040)
__device__ __forceinline__ void stage32(uint32_t A, const __half* __restrict__ gact,
                                        int r0, int tid) {
    uint4 pf[4];
    #pragma unroll
    for (int u = 0; u < 4; u++) {
        int i = u * 512 + tid;
        pf[u] = __ldcg((const uint4*)(gact + (size_t)(r0 + (i >> 6)) * Hsz + (i & 63) * 8));
    }
    #pragma unroll
    for (int u = 0; u < 4; u++) {
        int i = u * 512 + tid;
        sts16(A + (uint32_t)((i >> 6) * 1040 + (i & 63) * 16), pf[u]);
    }
}

// 16x8 warp-tile fp16 GEMM over k range [k0, k0+KS*16)
template<int KS>
__device__ __forceinline__ void mma_tile(uint32_t sb, uint32_t woff, int k0,
                                         int l, int wr0, int wn0, float d[4]) {
    uint32_t Ab = sb + OFF_ACT;
    uint32_t aoff = (uint32_t)((wr0 + (l & 15)) * 1040 + ((l >> 4) * 8) * 2 + k0 * 2);
    uint32_t boff = (uint32_t)((wn0 + (l & 7)) * 1040 + (l >> 3) * 16 + k0 * 2);
    float c0[4] = {0,0,0,0}, c1[4] = {0,0,0,0};
    #pragma unroll
    for (int it = 0; it < KS / 2; it++) {
        uint32_t a0[4], a1[4], b[4];
        ldsm4(a0[0], a0[1], a0[2], a0[3], Ab + aoff + it * 64);
        ldsm4(a1[0], a1[1], a1[2], a1[3], Ab + aoff + it * 64 + 32);
        ldsm4(b[0], b[1], b[2], b[3], sb + woff + boff + it * 64);
        mma_f16(c0, a0, b[0], b[1]);
        mma_f16(c1, a1, b[2], b[3]);
    }
    #pragma unroll
    for (int i = 0; i < 4; i++) d[i] = c0[i] + c1[i];
}

// ---------------- persistent recurrent loop kernel (512 thr, 2-group ilv) -----
__global__ __launch_bounds__(512, 1) void loop_kernel(float* __restrict__ out) {
    extern __shared__ char smem[];
    uint32_t sb = smem_u32(smem);
    int tid = threadIdx.x, cta = blockIdx.x;
    int wid = tid >> 5, l = tid & 31;

    int q = cta & 15;
    int gg0 = cta >> 4;                        // serves groups gg0 and gg0+8
    int sA  = q >> 3;                          // 0 = z, 1 = r
    int jA0 = (q & 7) * 64;
    int jB0 = q * 32;
    const __half* WAhi = g_Wh + (size_t)sA * Hsz * Hsz;
    const __half* WBhi = g_Wh + (size_t)2 * Hsz * Hsz;

    // one-time: hi weights into smem (1040B row stride)
    for (int i = tid; i < 4096; i += 512) {
        int r = i >> 6, s = i & 63;
        cpa16(sb + OFF_WA + r * 1040 + s * 16, WAhi + (size_t)(jA0 + r) * Hsz + s * 8);
    }
    for (int i = tid; i < 2048; i += 512) {
        int r = i >> 6, s = i & 63;
        cpa16(sb + OFF_WB + r * 1040 + s * 16, WBhi + (size_t)(jB0 + r) * Hsz + s * 8);
    }
    asm volatile("cp.async.commit_group;" ::: "memory");
    asm volatile("cp.async.wait_group 0;" ::: "memory");

    __half zh = __float2half(0.f);
    for (int i = tid; i < 2048; i += 512) {
        int o = cta * 2048 + i;
        g_HD[o] = 0.f;
        g_hd_h[o] = zh;
    }
    int grp[2] = {gg0, gg0 + 8};
    unsigned tg[2] = {16u, 16u};
    arrive_g(grp[0]);
    arrive_g(grp[1]);

    // warp layouts: A: 16 warps, 2x8 of 16x8 over 32x64.  B: 8 slots 2x4 of
    // 16x8 over 32x32, K split between warp w (k<256) and w+8 (k>=256).
    int wr0A = (wid & 1) * 16, wn0A = (wid >> 1) * 8;
    int widB = wid & 7;
    int wr0B = (widB & 1) * 16, wn0B = (widB >> 1) * 8;
    int kB0  = (wid < 8) ? 0 : 256;

    for (int t = 0; t < Tsz; t++) {
        // ================== phase A for both groups ==========================
        #pragma unroll 1
        for (int pi = 0; pi < 2; pi++) {
            int g = grp[pi];
            wait_g(g, tg[pi]); tg[pi] += 16;
            int rA0 = g * 32;
            stage32(sb + OFF_ACT, g_hd_h, rA0, tid);
            const float* At = g_A + (size_t)sA * TBH + (size_t)t * BH;
            int col = jA0 + wn0A + (l & 3) * 2;
            float2 atv[2], hdv[2];
            #pragma unroll
            for (int h = 0; h < 2; h++) {
                int row = rA0 + wr0A + (l >> 2) + h * 8;
                size_t o = (size_t)row * Hsz + col;
                atv[h] = __ldcg((const float2*)(At + o));
                if (sA) hdv[h] = __ldcg((const float2*)(g_HD + o));
            }
            __syncthreads();
            float d[4];
            mma_tile<32>(sb, OFF_WA, 0, l, wr0A, wn0A, d);
            #pragma unroll
            for (int h = 0; h < 2; h++) {
                int row = rA0 + wr0A + (l >> 2) + h * 8;
                size_t o = (size_t)row * Hsz + col;
                float s0 = sigm(d[h * 2]     + atv[h].x);
                float s1 = sigm(d[h * 2 + 1] + atv[h].y);
                if (sA == 0) {
                    float2 zz = {s0, s1};
                    *(float2*)(g_Z + o) = zz;
                } else {
                    __half2 hp;
                    hp.x = __float2half(s0 * hdv[h].x);
                    hp.y = __float2half(s1 * hdv[h].y);
                    *(__half2*)(g_rh_h + o) = hp;
                }
            }
            arrive_g(g);
        }

        // ================== phase B for both groups ==========================
        #pragma unroll 1
        for (int pi = 0; pi < 2; pi++) {
            int g = grp[pi];
            wait_g(g, tg[pi]); tg[pi] += 16;
            int rB0 = g * 32;
            stage32(sb + OFF_ACT, g_rh_h, rB0, tid);
            const float* An = g_A + (size_t)2 * TBH + (size_t)t * BH;
            const float* ghn = g_gh + (size_t)(t + 1) * BH;
            bool last = (t == Tsz - 1);
            int col = jB0 + wn0B + (l & 3) * 2;
            float2 anv[2], ghv[2], zv[2], hdv[2];
            if (wid < 8) {
                #pragma unroll
                for (int h = 0; h < 2; h++) {
                    int row = rB0 + wr0B + (l >> 2) + h * 8;
                    size_t o = (size_t)row * Hsz + col;
                    anv[h] = __ldcg((const float2*)(An + o));
                    zv[h]  = __ldcg((const float2*)(g_Z + o));
                    hdv[h] = __ldcg((const float2*)(g_HD + o));
                    if (!last) ghv[h] = __ldcg((const float2*)(ghn + o));
                }
            }
            __syncthreads();
            float d[4];
            mma_tile<16>(sb, OFF_WB, kB0, l, wr0B, wn0B, d);
            // k-split reduction: warps 8-15 deposit partials, warps 0-7 add
            if (wid >= 8) {
                uint32_t ra = sb + OFF_RED + (uint32_t)(widB * 512 + l * 16);
                uint4 v = {__float_as_uint(d[0]), __float_as_uint(d[1]),
                           __float_as_uint(d[2]), __float_as_uint(d[3])};
                sts16(ra, v);
            }
            __syncthreads();
            if (wid < 8) {
                uint32_t ra = sb + OFF_RED + (uint32_t)(widB * 512 + l * 16);
                uint4 v = *(const uint4*)(smem + (ra - sb));
                d[0] += __uint_as_float(v.x);
                d[1] += __uint_as_float(v.y);
                d[2] += __uint_as_float(v.z);
                d[3] += __uint_as_float(v.w);
                #pragma unroll
                for (int h = 0; h < 2; h++) {
                    int row = rB0 + wr0B + (l >> 2) + h * 8;
                    size_t o = (size_t)row * Hsz + col;
                    #pragma unroll
                    for (int q2 = 0; q2 < 2; q2++) {
                        float ht = tanhf(d[h * 2 + q2] + (q2 ? anv[h].y : anv[h].x));
                        float z  = q2 ? zv[h].y : zv[h].x;
                        float hd = q2 ? hdv[h].y : hdv[h].x;
                        float hp = (1.f - z) * hd + z * ht;
                        if (last) {
                            out[o + q2] = hp;
                        } else {
                            float hdn = (q2 ? ghv[h].y : ghv[h].x) * hp;
                            g_HD[o + q2] = hdn;
                            g_hd_h[o + q2] = __float2half(hdn);
                        }
                    }
                }
            }
            arrive_g(g);
        }
    }
}

// ---------------- launch ----------------
extern "C" void kernel_launch(void* const* d_in, const int* in_sizes, int n_in,
                              void* d_out, int out_size) {
    const float* x    = (const float*)d_in[0];
    const float* xl   = (const float*)d_in[1];
    const float* mk   = (const float*)d_in[2];
    const float* dl   = (const float*)d_in[3];
    const float* xm   = (const float*)d_in[4];
    const float* Wz   = (const float*)d_in[5];
    const float* bz   = (const float*)d_in[6];
    const float* Wr   = (const float*)d_in[7];
    const float* br   = (const float*)d_in[8];
    const float* Wn   = (const float*)d_in[9];
    const float* bn   = (const float*)d_in[10];
    const float* Wgx  = (const float*)d_in[11];
    const float* bgx  = (const float*)d_in[12];
    const float* Wgh  = (const float*)d_in[13];
    const float* bgh  = (const float*)d_in[14];

    static int smem_set = 0;
    if (!smem_set) {
        cudaFuncSetAttribute(loop_kernel,
                             cudaFuncAttributeMaxDynamicSharedMemorySize, SMEM_TOTAL);
        cudaFuncSetAttribute(p12_kernel,
                             cudaFuncAttributeMaxDynamicSharedMemorySize, PG_SMEM);
        smem_set = 1;
    }

    p0prep_kernel<<<65536 + 4864 + 1, 256>>>(x, xl, mk, dl, xm, Wgx, bgx,
                                             Wz, Wr, Wn, Wgh);
    p12_kernel<<<dim3(16, 1024), 256, PG_SMEM>>>(bz, br, bn, bgh);
    dummy_kernel<<<1, 32>>>();
    loop_kernel<<<NCTA, 512, SMEM_TOTAL>>>((float*)d_out);
}

// round 12
// speedup vs baseline: 1.9316x; 1.1184x over previous
#include <cuda_runtime.h>
#include <cuda_fp16.h>
#include <cstdint>

#define Bsz 512
#define Tsz 256
#define Dsz 128
#define Hsz 512
#define GIN 768
#define TB  (Tsz*Bsz)          /* 131072 */
#define BH  (Bsz*Hsz)          /* 262144 */
#define NCTA 128

static const size_t TBH = (size_t)TB * Hsz;   /* 67108864 */

// loop-kernel smem (bytes): WA 64x1040, WB 32x1040, ACT 32x1040, RED 4KB
#define OFF_WA  0u
#define OFF_WB  66560u
#define OFF_ACT 99840u
#define OFF_RED 133120u
#define SMEM_TOTAL 137216

// precompute-gemm smem: 2 bufs x 3 tiles x (128 rows x 144B)
#define PG_TILE 18432u
#define PG_BUF  55296u
#define PG_SMEM 110592

// ---------------- scratch (__device__ globals: allocation-free) ----------------
__device__ float g_A [201326592];       // 3 x (T*B, H): affine terms (bias incl.)
__device__ float g_gh[67108864];        // (T*B, H): hidden decay gamma_h
__device__ float g_HD[BH];              // hd = gh*h (fp32)
__device__ float g_Z [BH];              // z gate
__device__ __half g_x1h[TB*256];        // [xt|m] fp16
__device__ __half g_dh [TB*128];        // delta fp16
__device__ __half g_hd_h[BH];           // hd fp16
__device__ __half g_rh_h[BH];           // r*hd fp16
__device__ __half g_Wh[3*Hsz*Hsz];      // hidden slices (hi only)
__device__ __half g_W1hh[3*Hsz*256], g_W1hl[3*Hsz*256]; // x|m slices hi/lo
__device__ __half g_Wghh[Hsz*128], g_Wghl[Hsz*128];     // Wgh hi/lo
__device__ unsigned g_bar[512];         // 16 group counters, 128B apart

// ---------------- small helpers ----------------
__device__ __forceinline__ float sigm(float x) { return 1.f / (1.f + expf(-x)); }
__device__ __forceinline__ uint32_t smem_u32(const void* p) {
    uint32_t a;
    asm("{ .reg .u64 t; cvta.to.shared.u64 t, %1; cvt.u32.u64 %0, t; }" : "=r"(a) : "l"(p));
    return a;
}
__device__ __forceinline__ void cpa16(uint32_t dst, const void* src) {
    asm volatile("cp.async.cg.shared.global [%0],[%1],16;" :: "r"(dst), "l"(src));
}
__device__ __forceinline__ void sts16(uint32_t a, uint4 v) {
    asm volatile("st.shared.v4.b32 [%0],{%1,%2,%3,%4};"
                 :: "r"(a), "r"(v.x), "r"(v.y), "r"(v.z), "r"(v.w));
}
__device__ __forceinline__ void ldsm4(uint32_t &r0, uint32_t &r1, uint32_t &r2,
                                      uint32_t &r3, uint32_t addr) {
    asm volatile("ldmatrix.sync.aligned.m8n8.x4.shared.b16 {%0,%1,%2,%3},[%4];"
                 : "=r"(r0), "=r"(r1), "=r"(r2), "=r"(r3) : "r"(addr));
}
__device__ __forceinline__ void mma_f16(float* d, const uint32_t* a,
                                        uint32_t b0, uint32_t b1) {
    asm volatile("mma.sync.aligned.m16n8k16.row.col.f32.f16.f16.f32 "
                 "{%0,%1,%2,%3},{%4,%5,%6,%7},{%8,%9},{%0,%1,%2,%3};"
                 : "+f"(d[0]), "+f"(d[1]), "+f"(d[2]), "+f"(d[3])
                 : "r"(a[0]), "r"(a[1]), "r"(a[2]), "r"(a[3]), "r"(b0), "r"(b1));
}

// ---------------- group barrier primitives (16 CTAs per group) ----------------
// release-arrive / acquire-wait (syncthreads HB + gpu-scope rel/acq pair)
__device__ __forceinline__ void arrive_g(int g) {
    __syncthreads();
    if (threadIdx.x == 0) {
        asm volatile("red.release.gpu.global.add.u32 [%0],%1;"
                     :: "l"(g_bar + g * 32), "r"(1u) : "memory");
    }
}
__device__ __forceinline__ void wait_g(int g, unsigned target) {
    if (threadIdx.x == 0) {
        unsigned v;
        do {
            asm volatile("ld.acquire.gpu.global.u32 %0,[%1];"
                         : "=r"(v) : "l"(g_bar + g * 32) : "memory");
        } while (v < target);
    }
    __syncthreads();
}

// ---------------- K0: fused p0 (input decay staging) + weight split + bar -----
__global__ void p0prep_kernel(const float* __restrict__ x,  const float* __restrict__ xl,
                              const float* __restrict__ mk, const float* __restrict__ dl,
                              const float* __restrict__ xmean,
                              const float* __restrict__ Wgx, const float* __restrict__ bgx,
                              const float* __restrict__ Wz, const float* __restrict__ Wr,
                              const float* __restrict__ Wn, const float* __restrict__ Wgh) {
    int bx = blockIdx.x;
    if (bx < 65536) {
        int idx = bx * 256 + threadIdx.x;
        int d   = idx & 127;
        int row = idx >> 7;
        int t   = row >> 9;
        int b   = row & 511;
        size_t xi = ((size_t)b * Tsz + t) * Dsz + d;
        float dv = dl[xi], mv = mk[xi];
        float gx = expf(-fmaxf(0.f, dv * Wgx[d * Dsz + d] + bgx[d]));
        float xt = mv * x[xi] + (1.f - mv) * (gx * xl[xi] + (1.f - gx) * xmean[d]);
        g_x1h[(size_t)row * 256 + d]       = __float2half(xt);
        g_x1h[(size_t)row * 256 + 128 + d] = __float2half(mv);
        g_dh [(size_t)row * 128 + d]       = __float2half(dv);
    } else if (bx < 65536 + 4864) {
        int idx = (bx - 65536) * 256 + threadIdx.x;
        if (idx < 786432) {                 // hidden slices (hi only)
            int k = idx & 511, j = (idx >> 9) & 511, g = idx >> 18;
            const float* W = (g == 0) ? Wz : (g == 1) ? Wr : Wn;
            g_Wh[idx] = __float2half(W[(size_t)j * GIN + 128 + k]);
        } else if (idx < 786432 + 393216) { // x|m slices hi/lo
            int e = idx - 786432;
            int k = e & 255, j = (e >> 8) & 511, g = e >> 17;
            const float* W = (g == 0) ? Wz : (g == 1) ? Wr : Wn;
            int col = (k < 128) ? k : (512 + k);
            float w = W[(size_t)j * GIN + col];
            __half hi = __float2half(w);
            g_W1hh[e] = hi;
            g_W1hl[e] = __float2half(w - __half2float(hi));
        } else if (idx < 786432 + 393216 + 65536) {
            int e = idx - 786432 - 393216;
            float w = Wgh[e];
            __half hi = __float2half(w);
            g_Wghh[e] = hi;
            g_Wghl[e] = __float2half(w - __half2float(hi));
        }
    } else {
        g_bar[threadIdx.x] = 0u;
        g_bar[threadIdx.x + 256] = 0u;
    }
}

// ---------------- precompute GEMM core (fp16 2-term weights) ------------------
template<int KCH>
__device__ __forceinline__ void pg_core(uint32_t sb,
        const __half* __restrict__ Ah,
        const __half* __restrict__ Bh, const __half* __restrict__ Bl,
        int row0, int j0, int K, int tid, float d[2][8][4]) {
    #pragma unroll
    for (int mt = 0; mt < 2; mt++)
        #pragma unroll
        for (int nf = 0; nf < 8; nf++)
            #pragma unroll
            for (int i = 0; i < 4; i++) d[mt][nf][i] = 0.f;

    int wid = tid >> 5, l = tid & 31;
    int wr0 = (wid >> 1) * 32;
    int wn0 = (wid & 1) * 64;
    uint32_t aoff = (uint32_t)((wr0 + (l & 15)) * 144 + ((l >> 4) * 8) * 2);
    uint32_t boff = (uint32_t)((wn0 + ((l >> 4) << 3) + (l & 7)) * 144
                               + (((l >> 3) & 1) * 8) * 2);
    int sr = tid >> 3, ss = tid & 7;

    #pragma unroll
    for (int u = 0; u < 4; u++) {
        int r = sr + u * 32;
        uint32_t db = sb + (uint32_t)(r * 144 + ss * 16);
        cpa16(db,               Ah + (size_t)(row0 + r) * K + ss * 8);
        cpa16(db + PG_TILE,     Bh + (size_t)(j0 + r) * K + ss * 8);
        cpa16(db + 2 * PG_TILE, Bl + (size_t)(j0 + r) * K + ss * 8);
    }
    asm volatile("cp.async.commit_group;" ::: "memory");

    for (int c = 0; c < KCH; c++) {
        if (c + 1 < KCH) {
            uint32_t bb = sb + ((c + 1) & 1) * PG_BUF;
            #pragma unroll
            for (int u = 0; u < 4; u++) {
                int r = sr + u * 32;
                uint32_t db = bb + (uint32_t)(r * 144 + ss * 16);
                int ko = (c + 1) * 64 + ss * 8;
                cpa16(db,               Ah + (size_t)(row0 + r) * K + ko);
                cpa16(db + PG_TILE,     Bh + (size_t)(j0 + r) * K + ko);
                cpa16(db + 2 * PG_TILE, Bl + (size_t)(j0 + r) * K + ko);
            }
            asm volatile("cp.async.commit_group;" ::: "memory");
            asm volatile("cp.async.wait_group 1;" ::: "memory");
        } else {
            asm volatile("cp.async.wait_group 0;" ::: "memory");
        }
        __syncthreads();
        uint32_t bb = sb + (c & 1) * PG_BUF;
        #pragma unroll
        for (int ks = 0; ks < 4; ks++) {
            uint32_t ko = (uint32_t)(ks * 32);
            uint32_t ah[2][4], bh[4][4], bl[4][4];
            #pragma unroll
            for (int mt = 0; mt < 2; mt++) {
                uint32_t a = bb + aoff + (uint32_t)(mt * 16 * 144) + ko;
                ldsm4(ah[mt][0], ah[mt][1], ah[mt][2], ah[mt][3], a);
            }
            #pragma unroll
            for (int p = 0; p < 4; p++) {
                uint32_t b = bb + PG_TILE + boff + (uint32_t)(p * 16 * 144) + ko;
                ldsm4(bh[p][0], bh[p][1], bh[p][2], bh[p][3], b);
                ldsm4(bl[p][0], bl[p][1], bl[p][2], bl[p][3], b + PG_TILE);
            }
            #pragma unroll
            for (int p = 0; p < 4; p++)
                #pragma unroll
                for (int mt = 0; mt < 2; mt++) {
                    mma_f16(d[mt][2*p],   ah[mt], bh[p][0], bh[p][1]);
                    mma_f16(d[mt][2*p+1], ah[mt], bh[p][2], bh[p][3]);
                }
            #pragma unroll
            for (int p = 0; p < 4; p++)
                #pragma unroll
                for (int mt = 0; mt < 2; mt++) {
                    mma_f16(d[mt][2*p],   ah[mt], bl[p][0], bl[p][1]);
                    mma_f16(d[mt][2*p+1], ah[mt], bl[p][2], bl[p][3]);
                }
        }
        __syncthreads();
    }
}

// ---------------- K1: fused p1m + p2m -----------------------------------------
__global__ __launch_bounds__(256, 2) void p12_kernel(
        const float* __restrict__ bz, const float* __restrict__ br,
        const float* __restrict__ bn, const float* __restrict__ bgh) {
    extern __shared__ char smem[];
    uint32_t sb = smem_u32(smem);
    int tid = threadIdx.x;
    int row0 = blockIdx.y * 128;
    int wid = tid >> 5, l = tid & 31;
    int wr0 = (wid >> 1) * 32, wn0 = (wid & 1) * 64;
    float d[2][8][4];
    if (blockIdx.x < 12) {
        int s = blockIdx.x >> 2;
        int j0 = (blockIdx.x & 3) * 128;
        const float* bias = (s == 0) ? bz : (s == 1) ? br : bn;
        float* out = g_A + (size_t)s * TBH;
        pg_core<4>(sb, g_x1h,
                   g_W1hh + (size_t)s * Hsz * 256, g_W1hl + (size_t)s * Hsz * 256,
                   row0, j0, 256, tid, d);
        #pragma unroll
        for (int mt = 0; mt < 2; mt++)
            #pragma unroll
            for (int nf = 0; nf < 8; nf++)
                #pragma unroll
                for (int h = 0; h < 2; h++) {
                    int row = row0 + wr0 + mt * 16 + (l >> 2) + h * 8;
                    int col = j0 + wn0 + nf * 8 + (l & 3) * 2;
                    float2 v;
                    v.x = d[mt][nf][h * 2]     + bias[col];
                    v.y = d[mt][nf][h * 2 + 1] + bias[col + 1];
                    *(float2*)(out + (size_t)row * Hsz + col) = v;
                }
    } else {
        int j0 = (blockIdx.x - 12) * 128;
        pg_core<2>(sb, g_dh, g_Wghh, g_Wghl, row0, j0, 128, tid, d);
        #pragma unroll
        for (int mt = 0; mt < 2; mt++)
            #pragma unroll
            for (int nf = 0; nf < 8; nf++)
                #pragma unroll
                for (int h = 0; h < 2; h++) {
                    int row = row0 + wr0 + mt * 16 + (l >> 2) + h * 8;
                    int col = j0 + wn0 + nf * 8 + (l & 3) * 2;
                    float2 v;
                    v.x = expf(-fmaxf(0.f, d[mt][nf][h * 2]     + bgh[col]));
                    v.y = expf(-fmaxf(0.f, d[mt][nf][h * 2 + 1] + bgh[col + 1]));
                    *(float2*)(g_gh + (size_t)row * Hsz + col) = v;
                }
    }
}

__global__ void dummy_kernel() {}

// ---------------- loop helpers ------------------------------------------------
// issue cp.async staging of a 32x512 fp16 act tile (stride 1040); caller waits
__device__ __forceinline__ void stage32_issue(uint32_t A, const __half* __restrict__ gact,
                                              int r0, int tid) {
    #pragma unroll
    for (int u = 0; u < 4; u++) {
        int i = u * 512 + tid;
        cpa16(A + (uint32_t)((i >> 6) * 1040 + (i & 63) * 16),
              gact + (size_t)(r0 + (i >> 6)) * Hsz + (i & 63) * 8);
    }
    asm volatile("cp.async.commit_group;" ::: "memory");
}
__device__ __forceinline__ void stage_wait() {
    asm volatile("cp.async.wait_group 0;" ::: "memory");
    __syncthreads();
}

// 16x8 warp-tile fp16 GEMM over k range [k0, k0+KS*16); 4 accumulator chains
template<int KS>
__device__ __forceinline__ void mma_tile(uint32_t sb, uint32_t woff, int k0,
                                         int l, int wr0, int wn0, float d[4]) {
    uint32_t Ab = sb + OFF_ACT;
    uint32_t aoff = (uint32_t)((wr0 + (l & 15)) * 1040 + ((l >> 4) * 8) * 2 + k0 * 2);
    uint32_t boff = (uint32_t)((wn0 + (l & 7)) * 1040 + (l >> 3) * 16 + k0 * 2);
    float c0[4] = {0,0,0,0}, c1[4] = {0,0,0,0};
    float c2[4] = {0,0,0,0}, c3[4] = {0,0,0,0};
    #pragma unroll
    for (int it = 0; it < KS / 2; it++) {
        uint32_t a0[4], a1[4], b[4];
        ldsm4(a0[0], a0[1], a0[2], a0[3], Ab + aoff + it * 64);
        ldsm4(a1[0], a1[1], a1[2], a1[3], Ab + aoff + it * 64 + 32);
        ldsm4(b[0], b[1], b[2], b[3], sb + woff + boff + it * 64);
        if (it & 1) {
            mma_f16(c2, a0, b[0], b[1]);
            mma_f16(c3, a1, b[2], b[3]);
        } else {
            mma_f16(c0, a0, b[0], b[1]);
            mma_f16(c1, a1, b[2], b[3]);
        }
    }
    #pragma unroll
    for (int i = 0; i < 4; i++) d[i] = (c0[i] + c1[i]) + (c2[i] + c3[i]);
}

// ---------------- persistent recurrent loop kernel (512 thr, 2-group ilv) -----
__global__ __launch_bounds__(512, 1) void loop_kernel(float* __restrict__ out) {
    extern __shared__ char smem[];
    uint32_t sb = smem_u32(smem);
    int tid = threadIdx.x, cta = blockIdx.x;
    int wid = tid >> 5, l = tid & 31;

    int q = cta & 15;
    int gg0 = cta >> 4;                        // serves groups gg0 and gg0+8
    int sA  = q >> 3;                          // 0 = z, 1 = r
    int jA0 = (q & 7) * 64;
    int jB0 = q * 32;
    const __half* WAhi = g_Wh + (size_t)sA * Hsz * Hsz;
    const __half* WBhi = g_Wh + (size_t)2 * Hsz * Hsz;

    // one-time: hi weights into smem (1040B row stride)
    for (int i = tid; i < 4096; i += 512) {
        int r = i >> 6, s = i & 63;
        cpa16(sb + OFF_WA + r * 1040 + s * 16, WAhi + (size_t)(jA0 + r) * Hsz + s * 8);
    }
    for (int i = tid; i < 2048; i += 512) {
        int r = i >> 6, s = i & 63;
        cpa16(sb + OFF_WB + r * 1040 + s * 16, WBhi + (size_t)(jB0 + r) * Hsz + s * 8);
    }
    asm volatile("cp.async.commit_group;" ::: "memory");
    asm volatile("cp.async.wait_group 0;" ::: "memory");

    __half zh = __float2half(0.f);
    for (int i = tid; i < 2048; i += 512) {
        int o = cta * 2048 + i;
        g_HD[o] = 0.f;
        g_hd_h[o] = zh;
    }
    int grp[2] = {gg0, gg0 + 8};
    unsigned tg[2] = {16u, 16u};
    arrive_g(grp[0]);
    arrive_g(grp[1]);

    // warp layouts: A: 16 warps, 2x8 of 16x8 over 32x64.  B: 8 slots 2x4 of
    // 16x8 over 32x32, K split between warp w (k<256) and w+8 (k>=256).
    int wr0A = (wid & 1) * 16, wn0A = (wid >> 1) * 8;
    int widB = wid & 7;
    int wr0B = (widB & 1) * 16, wn0B = (widB >> 1) * 8;
    int kB0  = (wid < 8) ? 0 : 256;

    for (int t = 0; t < Tsz; t++) {
        // ================== phase A for both groups ==========================
        #pragma unroll 1
        for (int pi = 0; pi < 2; pi++) {
            int g = grp[pi];
            wait_g(g, tg[pi]); tg[pi] += 16;
            int rA0 = g * 32;
            stage32_issue(sb + OFF_ACT, g_hd_h, rA0, tid);
            const float* At = g_A + (size_t)sA * TBH + (size_t)t * BH;
            int col = jA0 + wn0A + (l & 3) * 2;
            float2 atv[2], hdv[2];
            #pragma unroll
            for (int h = 0; h < 2; h++) {
                int row = rA0 + wr0A + (l >> 2) + h * 8;
                size_t o = (size_t)row * Hsz + col;
                atv[h] = __ldcg((const float2*)(At + o));
                if (sA) hdv[h] = __ldcg((const float2*)(g_HD + o));
            }
            stage_wait();
            float d[4];
            mma_tile<32>(sb, OFF_WA, 0, l, wr0A, wn0A, d);
            #pragma unroll
            for (int h = 0; h < 2; h++) {
                int row = rA0 + wr0A + (l >> 2) + h * 8;
                size_t o = (size_t)row * Hsz + col;
                float s0 = sigm(d[h * 2]     + atv[h].x);
                float s1 = sigm(d[h * 2 + 1] + atv[h].y);
                if (sA == 0) {
                    float2 zz = {s0, s1};
                    *(float2*)(g_Z + o) = zz;
                } else {
                    __half2 hp;
                    hp.x = __float2half(s0 * hdv[h].x);
                    hp.y = __float2half(s1 * hdv[h].y);
                    *(__half2*)(g_rh_h + o) = hp;
                }
            }
            arrive_g(g);
        }

        // ================== phase B for both groups ==========================
        #pragma unroll 1
        for (int pi = 0; pi < 2; pi++) {
            int g = grp[pi];
            wait_g(g, tg[pi]); tg[pi] += 16;
            int rB0 = g * 32;
            stage32_issue(sb + OFF_ACT, g_rh_h, rB0, tid);
            const float* An = g_A + (size_t)2 * TBH + (size_t)t * BH;
            const float* ghn = g_gh + (size_t)(t + 1) * BH;
            bool last = (t == Tsz - 1);
            int col = jB0 + wn0B + (l & 3) * 2;
            float2 anv[2], ghv[2], zv[2], hdv[2];
            if (wid < 8) {
                #pragma unroll
                for (int h = 0; h < 2; h++) {
                    int row = rB0 + wr0B + (l >> 2) + h * 8;
                    size_t o = (size_t)row * Hsz + col;
                    anv[h] = __ldcg((const float2*)(An + o));
                    zv[h]  = __ldcg((const float2*)(g_Z + o));
                    hdv[h] = __ldcg((const float2*)(g_HD + o));
                    if (!last) ghv[h] = __ldcg((const float2*)(ghn + o));
                }
            }
            stage_wait();
            float d[4];
            mma_tile<16>(sb, OFF_WB, kB0, l, wr0B, wn0B, d);
            // k-split reduction: warps 8-15 deposit partials, warps 0-7 add
            if (wid >= 8) {
                uint32_t ra = sb + OFF_RED + (uint32_t)(widB * 512 + l * 16);
                uint4 v = {__float_as_uint(d[0]), __float_as_uint(d[1]),
                           __float_as_uint(d[2]), __float_as_uint(d[3])};
                sts16(ra, v);
            }
            __syncthreads();
            if (wid < 8) {
                uint32_t ra = sb + OFF_RED + (uint32_t)(widB * 512 + l * 16);
                uint4 v = *(const uint4*)(smem + (ra - sb));
                d[0] += __uint_as_float(v.x);
                d[1] += __uint_as_float(v.y);
                d[2] += __uint_as_float(v.z);
                d[3] += __uint_as_float(v.w);
                #pragma unroll
                for (int h = 0; h < 2; h++) {
                    int row = rB0 + wr0B + (l >> 2) + h * 8;
                    size_t o = (size_t)row * Hsz + col;
                    #pragma unroll
                    for (int q2 = 0; q2 < 2; q2++) {
                        float ht = tanhf(d[h * 2 + q2] + (q2 ? anv[h].y : anv[h].x));
                        float z  = q2 ? zv[h].y : zv[h].x;
                        float hd = q2 ? hdv[h].y : hdv[h].x;
                        float hp = (1.f - z) * hd + z * ht;
                        if (last) {
                            out[o + q2] = hp;
                        } else {
                            float hdn = (q2 ? ghv[h].y : ghv[h].x) * hp;
                            g_HD[o + q2] = hdn;
                            g_hd_h[o + q2] = __float2half(hdn);
                        }
                    }
                }
            }
            arrive_g(g);
        }
    }
}

// ---------------- launch ----------------
extern "C" void kernel_launch(void* const* d_in, const int* in_sizes, int n_in,
                              void* d_out, int out_size) {
    const float* x    = (const float*)d_in[0];
    const float* xl   = (const float*)d_in[1];
    const float* mk   = (const float*)d_in[2];
    const float* dl   = (const float*)d_in[3];
    const float* xm   = (const float*)d_in[4];
    const float* Wz   = (const float*)d_in[5];
    const float* bz   = (const float*)d_in[6];
    const float* Wr   = (const float*)d_in[7];
    const float* br   = (const float*)d_in[8];
    const float* Wn   = (const float*)d_in[9];
    const float* bn   = (const float*)d_in[10];
    const float* Wgx  = (const float*)d_in[11];
    const float* bgx  = (const float*)d_in[12];
    const float* Wgh  = (const float*)d_in[13];
    const float* bgh  = (const float*)d_in[14];

    static int smem_set = 0;
    if (!smem_set) {
        cudaFuncSetAttribute(loop_kernel,
                             cudaFuncAttributeMaxDynamicSharedMemorySize, SMEM_TOTAL);
        cudaFuncSetAttribute(p12_kernel,
                             cudaFuncAttributeMaxDynamicSharedMemorySize, PG_SMEM);
        smem_set = 1;
    }

    p0prep_kernel<<<65536 + 4864 + 1, 256>>>(x, xl, mk, dl, xm, Wgx, bgx,
                                             Wz, Wr, Wn, Wgh);
    p12_kernel<<<dim3(16, 1024), 256, PG_SMEM>>>(bz, br, bn, bgh);
    dummy_kernel<<<1, 32>>>();
    loop_kernel<<<NCTA, 512, SMEM_TOTAL>>>((float*)d_out);
}

// round 13
// speedup vs baseline: 2.0719x; 1.0726x over previous
#include <cuda_runtime.h>
#include <cuda_fp16.h>
#include <cstdint>

#define Bsz 512
#define Tsz 256
#define Dsz 128
#define Hsz 512
#define GIN 768
#define TB  (Tsz*Bsz)          /* 131072 */
#define BH  (Bsz*Hsz)          /* 262144 */
#define NCTA 128

static const size_t TBH = (size_t)TB * Hsz;   /* 67108864 */

// loop-kernel smem (bytes): WA 64x1040, WB 32x1040, ACT 32x1040, RED 8KB
#define OFF_WA  0u
#define OFF_WB  66560u
#define OFF_ACT 99840u
#define OFF_RED 133120u
#define SMEM_TOTAL 141312

// precompute-gemm smem: 2 bufs x 2 tiles x (128 rows x 144B)
#define PG_TILE 18432u
#define PG_BUF  36864u
#define PG_SMEM 73728

// ---------------- scratch (__device__ globals: allocation-free) ----------------
__device__ float g_A [201326592];       // 3 x (T*B, H): affine terms (bias incl.)
__device__ float g_gh[67108864];        // (T*B, H): hidden decay gamma_h
__device__ float g_HD[BH];              // hd = gh*h (fp32)
__device__ float g_Z [BH];              // z gate
__device__ __half g_x1h[TB*256];        // [xt|m] fp16
__device__ __half g_dh [TB*128];        // delta fp16
__device__ __half g_hd_h[BH];           // hd fp16
__device__ __half g_rh_h[BH];           // r*hd fp16
__device__ __half g_Wh[3*Hsz*Hsz];      // hidden slices (hi only)
__device__ __half g_W1hh[3*Hsz*256];    // x|m slices (hi only)
__device__ __half g_Wghh[Hsz*128];      // Wgh (hi only)
__device__ unsigned g_bar[512];         // 16 group counters, 128B apart

// ---------------- small helpers ----------------
__device__ __forceinline__ float sigm(float x) { return 1.f / (1.f + expf(-x)); }
__device__ __forceinline__ uint32_t smem_u32(const void* p) {
    uint32_t a;
    asm("{ .reg .u64 t; cvta.to.shared.u64 t, %1; cvt.u32.u64 %0, t; }" : "=r"(a) : "l"(p));
    return a;
}
__device__ __forceinline__ void cpa16(uint32_t dst, const void* src) {
    asm volatile("cp.async.cg.shared.global [%0],[%1],16;" :: "r"(dst), "l"(src));
}
__device__ __forceinline__ void sts16(uint32_t a, uint4 v) {
    asm volatile("st.shared.v4.b32 [%0],{%1,%2,%3,%4};"
                 :: "r"(a), "r"(v.x), "r"(v.y), "r"(v.z), "r"(v.w));
}
__device__ __forceinline__ void ldsm4(uint32_t &r0, uint32_t &r1, uint32_t &r2,
                                      uint32_t &r3, uint32_t addr) {
    asm volatile("ldmatrix.sync.aligned.m8n8.x4.shared.b16 {%0,%1,%2,%3},[%4];"
                 : "=r"(r0), "=r"(r1), "=r"(r2), "=r"(r3) : "r"(addr));
}
__device__ __forceinline__ void mma_f16(float* d, const uint32_t* a,
                                        uint32_t b0, uint32_t b1) {
    asm volatile("mma.sync.aligned.m16n8k16.row.col.f32.f16.f16.f32 "
                 "{%0,%1,%2,%3},{%4,%5,%6,%7},{%8,%9},{%0,%1,%2,%3};"
                 : "+f"(d[0]), "+f"(d[1]), "+f"(d[2]), "+f"(d[3])
                 : "r"(a[0]), "r"(a[1]), "r"(a[2]), "r"(a[3]), "r"(b0), "r"(b1));
}

// ---------------- group barrier primitives (16 CTAs per group) ----------------
__device__ __forceinline__ void arrive_g(int g) {
    __syncthreads();
    if (threadIdx.x == 0) {
        asm volatile("red.release.gpu.global.add.u32 [%0],%1;"
                     :: "l"(g_bar + g * 32), "r"(1u) : "memory");
    }
}
__device__ __forceinline__ void wait_g(int g, unsigned target) {
    if (threadIdx.x == 0) {
        unsigned v;
        do {
            asm volatile("ld.acquire.gpu.global.u32 %0,[%1];"
                         : "=r"(v) : "l"(g_bar + g * 32) : "memory");
        } while (v < target);
    }
    __syncthreads();
}

// ---------------- K0: fused p0 (input decay staging) + weight split + bar -----
__global__ void p0prep_kernel(const float* __restrict__ x,  const float* __restrict__ xl,
                              const float* __restrict__ mk, const float* __restrict__ dl,
                              const float* __restrict__ xmean,
                              const float* __restrict__ Wgx, const float* __restrict__ bgx,
                              const float* __restrict__ Wz, const float* __restrict__ Wr,
                              const float* __restrict__ Wn, const float* __restrict__ Wgh) {
    int bx = blockIdx.x;
    if (bx < 65536) {
        int idx = bx * 256 + threadIdx.x;
        int d   = idx & 127;
        int row = idx >> 7;
        int t   = row >> 9;
        int b   = row & 511;
        size_t xi = ((size_t)b * Tsz + t) * Dsz + d;
        float dv = dl[xi], mv = mk[xi];
        float gx = expf(-fmaxf(0.f, dv * Wgx[d * Dsz + d] + bgx[d]));
        float xt = mv * x[xi] + (1.f - mv) * (gx * xl[xi] + (1.f - gx) * xmean[d]);
        g_x1h[(size_t)row * 256 + d]       = __float2half(xt);
        g_x1h[(size_t)row * 256 + 128 + d] = __float2half(mv);
        g_dh [(size_t)row * 128 + d]       = __float2half(dv);
    } else if (bx < 65536 + 4864) {
        int idx = (bx - 65536) * 256 + threadIdx.x;
        if (idx < 786432) {                 // hidden slices (hi only)
            int k = idx & 511, j = (idx >> 9) & 511, g = idx >> 18;
            const float* W = (g == 0) ? Wz : (g == 1) ? Wr : Wn;
            g_Wh[idx] = __float2half(W[(size_t)j * GIN + 128 + k]);
        } else if (idx < 786432 + 393216) { // x|m slices (hi only)
            int e = idx - 786432;
            int k = e & 255, j = (e >> 8) & 511, g = e >> 17;
            const float* W = (g == 0) ? Wz : (g == 1) ? Wr : Wn;
            int col = (k < 128) ? k : (512 + k);
            g_W1hh[e] = __float2half(W[(size_t)j * GIN + col]);
        } else if (idx < 786432 + 393216 + 65536) {
            int e = idx - 786432 - 393216;
            g_Wghh[e] = __float2half(Wgh[e]);
        }
    } else {
        g_bar[threadIdx.x] = 0u;
        g_bar[threadIdx.x + 256] = 0u;
    }
}

// ---------------- precompute GEMM core (fp16 single-term) ---------------------
template<int KCH>
__device__ __forceinline__ void pg_core(uint32_t sb,
        const __half* __restrict__ Ah, const __half* __restrict__ Bh,
        int row0, int j0, int K, int tid, float d[2][8][4]) {
    #pragma unroll
    for (int mt = 0; mt < 2; mt++)
        #pragma unroll
        for (int nf = 0; nf < 8; nf++)
            #pragma unroll
            for (int i = 0; i < 4; i++) d[mt][nf][i] = 0.f;

    int wid = tid >> 5, l = tid & 31;
    int wr0 = (wid >> 1) * 32;
    int wn0 = (wid & 1) * 64;
    uint32_t aoff = (uint32_t)((wr0 + (l & 15)) * 144 + ((l >> 4) * 8) * 2);
    uint32_t boff = (uint32_t)((wn0 + ((l >> 4) << 3) + (l & 7)) * 144
                               + (((l >> 3) & 1) * 8) * 2);
    int sr = tid >> 3, ss = tid & 7;

    #pragma unroll
    for (int u = 0; u < 4; u++) {
        int r = sr + u * 32;
        uint32_t db = sb + (uint32_t)(r * 144 + ss * 16);
        cpa16(db,           Ah + (size_t)(row0 + r) * K + ss * 8);
        cpa16(db + PG_TILE, Bh + (size_t)(j0 + r) * K + ss * 8);
    }
    asm volatile("cp.async.commit_group;" ::: "memory");

    for (int c = 0; c < KCH; c++) {
        if (c + 1 < KCH) {
            uint32_t bb = sb + ((c + 1) & 1) * PG_BUF;
            #pragma unroll
            for (int u = 0; u < 4; u++) {
                int r = sr + u * 32;
                uint32_t db = bb + (uint32_t)(r * 144 + ss * 16);
                int ko = (c + 1) * 64 + ss * 8;
                cpa16(db,           Ah + (size_t)(row0 + r) * K + ko);
                cpa16(db + PG_TILE, Bh + (size_t)(j0 + r) * K + ko);
            }
            asm volatile("cp.async.commit_group;" ::: "memory");
            asm volatile("cp.async.wait_group 1;" ::: "memory");
        } else {
            asm volatile("cp.async.wait_group 0;" ::: "memory");
        }
        __syncthreads();
        uint32_t bb = sb + (c & 1) * PG_BUF;
        #pragma unroll
        for (int ks = 0; ks < 4; ks++) {
            uint32_t ko = (uint32_t)(ks * 32);
            uint32_t ah[2][4], bh[4][4];
            #pragma unroll
            for (int mt = 0; mt < 2; mt++) {
                uint32_t a = bb + aoff + (uint32_t)(mt * 16 * 144) + ko;
                ldsm4(ah[mt][0], ah[mt][1], ah[mt][2], ah[mt][3], a);
            }
            #pragma unroll
            for (int p = 0; p < 4; p++) {
                uint32_t b = bb + PG_TILE + boff + (uint32_t)(p * 16 * 144) + ko;
                ldsm4(bh[p][0], bh[p][1], bh[p][2], bh[p][3], b);
            }
            #pragma unroll
            for (int p = 0; p < 4; p++)
                #pragma unroll
                for (int mt = 0; mt < 2; mt++) {
                    mma_f16(d[mt][2*p],   ah[mt], bh[p][0], bh[p][1]);
                    mma_f16(d[mt][2*p+1], ah[mt], bh[p][2], bh[p][3]);
                }
        }
        __syncthreads();
    }
}

// ---------------- K1: fused p1m + p2m -----------------------------------------
__global__ __launch_bounds__(256, 2) void p12_kernel(
        const float* __restrict__ bz, const float* __restrict__ br,
        const float* __restrict__ bn, const float* __restrict__ bgh) {
    extern __shared__ char smem[];
    uint32_t sb = smem_u32(smem);
    int tid = threadIdx.x;
    int row0 = blockIdx.y * 128;
    int wid = tid >> 5, l = tid & 31;
    int wr0 = (wid >> 1) * 32, wn0 = (wid & 1) * 64;
    float d[2][8][4];
    if (blockIdx.x < 12) {
        int s = blockIdx.x >> 2;
        int j0 = (blockIdx.x & 3) * 128;
        const float* bias = (s == 0) ? bz : (s == 1) ? br : bn;
        float* out = g_A + (size_t)s * TBH;
        pg_core<4>(sb, g_x1h, g_W1hh + (size_t)s * Hsz * 256, row0, j0, 256, tid, d);
        #pragma unroll
        for (int mt = 0; mt < 2; mt++)
            #pragma unroll
            for (int nf = 0; nf < 8; nf++)
                #pragma unroll
                for (int h = 0; h < 2; h++) {
                    int row = row0 + wr0 + mt * 16 + (l >> 2) + h * 8;
                    int col = j0 + wn0 + nf * 8 + (l & 3) * 2;
                    float2 v;
                    v.x = d[mt][nf][h * 2]     + bias[col];
                    v.y = d[mt][nf][h * 2 + 1] + bias[col + 1];
                    *(float2*)(out + (size_t)row * Hsz + col) = v;
                }
    } else {
        int j0 = (blockIdx.x - 12) * 128;
        pg_core<2>(sb, g_dh, g_Wghh, row0, j0, 128, tid, d);
        #pragma unroll
        for (int mt = 0; mt < 2; mt++)
            #pragma unroll
            for (int nf = 0; nf < 8; nf++)
                #pragma unroll
                for (int h = 0; h < 2; h++) {
                    int row = row0 + wr0 + mt * 16 + (l >> 2) + h * 8;
                    int col = j0 + wn0 + nf * 8 + (l & 3) * 2;
                    float2 v;
                    v.x = expf(-fmaxf(0.f, d[mt][nf][h * 2]     + bgh[col]));
                    v.y = expf(-fmaxf(0.f, d[mt][nf][h * 2 + 1] + bgh[col + 1]));
                    *(float2*)(g_gh + (size_t)row * Hsz + col) = v;
                }
    }
}

__global__ void dummy_kernel() {}

// ---------------- loop helpers ------------------------------------------------
// issue cp.async staging of a 32x512 fp16 act tile (stride 1040); caller waits
__device__ __forceinline__ void stage32_issue(uint32_t A, const __half* __restrict__ gact,
                                              int r0, int tid) {
    #pragma unroll
    for (int u = 0; u < 4; u++) {
        int i = u * 512 + tid;
        cpa16(A + (uint32_t)((i >> 6) * 1040 + (i & 63) * 16),
              gact + (size_t)(r0 + (i >> 6)) * Hsz + (i & 63) * 8);
    }
    asm volatile("cp.async.commit_group;" ::: "memory");
}
__device__ __forceinline__ void stage_wait() {
    asm volatile("cp.async.wait_group 0;" ::: "memory");
    __syncthreads();
}

// 16x16 warp-tile fp16 GEMM over k range [k0, k0+KS*16); 8 accumulator chains
template<int KS>
__device__ __forceinline__ void mma_tileN2(uint32_t sb, uint32_t woff, int k0,
                                           int l, int wr0, int wn0, float d[2][4]) {
    uint32_t Ab = sb + OFF_ACT;
    uint32_t aoff = (uint32_t)((wr0 + (l & 15)) * 1040 + ((l >> 4) * 8) * 2 + k0 * 2);
    uint32_t b1o  = (uint32_t)((wn0 + (l & 7)) * 1040 + (l >> 3) * 16 + k0 * 2);
    uint32_t b2o  = b1o + 8 * 1040;
    float c[8][4];
    #pragma unroll
    for (int i = 0; i < 8; i++)
        #pragma unroll
        for (int j = 0; j < 4; j++) c[i][j] = 0.f;
    #pragma unroll
    for (int it = 0; it < KS / 2; it++) {
        uint32_t a0[4], a1[4], b1[4], b2[4];
        ldsm4(a0[0], a0[1], a0[2], a0[3], Ab + aoff + it * 64);
        ldsm4(a1[0], a1[1], a1[2], a1[3], Ab + aoff + it * 64 + 32);
        ldsm4(b1[0], b1[1], b1[2], b1[3], sb + woff + b1o + it * 64);
        ldsm4(b2[0], b2[1], b2[2], b2[3], sb + woff + b2o + it * 64);
        int p = (it & 1) * 4;
        mma_f16(c[p + 0], a0, b1[0], b1[1]);
        mma_f16(c[p + 1], a0, b2[0], b2[1]);
        mma_f16(c[p + 2], a1, b1[2], b1[3]);
        mma_f16(c[p + 3], a1, b2[2], b2[3]);
    }
    #pragma unroll
    for (int i = 0; i < 4; i++) {
        d[0][i] = (c[0][i] + c[2][i]) + (c[4][i] + c[6][i]);
        d[1][i] = (c[1][i] + c[3][i]) + (c[5][i] + c[7][i]);
    }
}

// 16x8 warp-tile fp16 GEMM (phase B), 4 accumulator chains
template<int KS>
__device__ __forceinline__ void mma_tile(uint32_t sb, uint32_t woff, int k0,
                                         int l, int wr0, int wn0, float d[4]) {
    uint32_t Ab = sb + OFF_ACT;
    uint32_t aoff = (uint32_t)((wr0 + (l & 15)) * 1040 + ((l >> 4) * 8) * 2 + k0 * 2);
    uint32_t boff = (uint32_t)((wn0 + (l & 7)) * 1040 + (l >> 3) * 16 + k0 * 2);
    float c0[4] = {0,0,0,0}, c1[4] = {0,0,0,0};
    float c2[4] = {0,0,0,0}, c3[4] = {0,0,0,0};
    #pragma unroll
    for (int it = 0; it < KS / 2; it++) {
        uint32_t a0[4], a1[4], b[4];
        ldsm4(a0[0], a0[1], a0[2], a0[3], Ab + aoff + it * 64);
        ldsm4(a1[0], a1[1], a1[2], a1[3], Ab + aoff + it * 64 + 32);
        ldsm4(b[0], b[1], b[2], b[3], sb + woff + boff + it * 64);
        if (it & 1) {
            mma_f16(c2, a0, b[0], b[1]);
            mma_f16(c3, a1, b[2], b[3]);
        } else {
            mma_f16(c0, a0, b[0], b[1]);
            mma_f16(c1, a1, b[2], b[3]);
        }
    }
    #pragma unroll
    for (int i = 0; i < 4; i++) d[i] = (c0[i] + c1[i]) + (c2[i] + c3[i]);
}

// ---------------- persistent recurrent loop kernel (512 thr, 2-group ilv) -----
__global__ __launch_bounds__(512, 1) void loop_kernel(float* __restrict__ out) {
    extern __shared__ char smem[];
    uint32_t sb = smem_u32(smem);
    int tid = threadIdx.x, cta = blockIdx.x;
    int wid = tid >> 5, l = tid & 31;

    int q = cta & 15;
    int gg0 = cta >> 4;                        // serves groups gg0 and gg0+8
    int sA  = q >> 3;                          // 0 = z, 1 = r
    int jA0 = (q & 7) * 64;
    int jB0 = q * 32;
    const __half* WAhi = g_Wh + (size_t)sA * Hsz * Hsz;
    const __half* WBhi = g_Wh + (size_t)2 * Hsz * Hsz;

    // one-time: hi weights into smem (1040B row stride)
    for (int i = tid; i < 4096; i += 512) {
        int r = i >> 6, s = i & 63;
        cpa16(sb + OFF_WA + r * 1040 + s * 16, WAhi + (size_t)(jA0 + r) * Hsz + s * 8);
    }
    for (int i = tid; i < 2048; i += 512) {
        int r = i >> 6, s = i & 63;
        cpa16(sb + OFF_WB + r * 1040 + s * 16, WBhi + (size_t)(jB0 + r) * Hsz + s * 8);
    }
    asm volatile("cp.async.commit_group;" ::: "memory");
    asm volatile("cp.async.wait_group 0;" ::: "memory");

    __half zh = __float2half(0.f);
    for (int i = tid; i < 2048; i += 512) {
        int o = cta * 2048 + i;
        g_HD[o] = 0.f;
        g_hd_h[o] = zh;
    }
    int grp[2] = {gg0, gg0 + 8};
    unsigned tg[2] = {16u, 16u};
    arrive_g(grp[0]);
    arrive_g(grp[1]);

    // phase A: 8 slots of 16x16 over 32x64, 2-way K-split (warps 8-15: k>=256)
    int widA = wid & 7;
    int wr0A = (widA & 1) * 16, wn0A = (widA >> 1) * 16;
    int kA0  = (wid < 8) ? 0 : 256;
    // phase B: 8 slots of 16x8 over 32x32, 2-way K-split
    int widB = wid & 7;
    int wr0B = (widB & 1) * 16, wn0B = (widB >> 1) * 8;
    int kB0  = (wid < 8) ? 0 : 256;

    for (int t = 0; t < Tsz; t++) {
        // ================== phase A for both groups ==========================
        #pragma unroll 1
        for (int pi = 0; pi < 2; pi++) {
            int g = grp[pi];
            wait_g(g, tg[pi]); tg[pi] += 16;
            int rA0 = g * 32;
            stage32_issue(sb + OFF_ACT, g_hd_h, rA0, tid);
            const float* At = g_A + (size_t)sA * TBH + (size_t)t * BH;
            float2 atv[2][2], hdv[2][2];
            if (wid < 8) {
                #pragma unroll
                for (int nf = 0; nf < 2; nf++)
                    #pragma unroll
                    for (int h = 0; h < 2; h++) {
                        int col = jA0 + wn0A + nf * 8 + (l & 3) * 2;
                        int row = rA0 + wr0A + (l >> 2) + h * 8;
                        size_t o = (size_t)row * Hsz + col;
                        atv[nf][h] = __ldcg((const float2*)(At + o));
                        if (sA) hdv[nf][h] = __ldcg((const float2*)(g_HD + o));
                    }
            }
            stage_wait();
            float d[2][4];
            mma_tileN2<16>(sb, OFF_WA, kA0, l, wr0A, wn0A, d);
            if (wid >= 8) {
                uint32_t ra = sb + OFF_RED + (uint32_t)(widA * 1024 + l * 32);
                uint4 v0 = {__float_as_uint(d[0][0]), __float_as_uint(d[0][1]),
                            __float_as_uint(d[0][2]), __float_as_uint(d[0][3])};
                uint4 v1 = {__float_as_uint(d[1][0]), __float_as_uint(d[1][1]),
                            __float_as_uint(d[1][2]), __float_as_uint(d[1][3])};
                sts16(ra, v0);
                sts16(ra + 16, v1);
            }
            __syncthreads();
            if (wid < 8) {
                uint32_t ra = sb + OFF_RED + (uint32_t)(widA * 1024 + l * 32);
                uint4 v0 = *(const uint4*)(smem + (ra - sb));
                uint4 v1 = *(const uint4*)(smem + (ra - sb) + 16);
                d[0][0] += __uint_as_float(v0.x); d[0][1] += __uint_as_float(v0.y);
                d[0][2] += __uint_as_float(v0.z); d[0][3] += __uint_as_float(v0.w);
                d[1][0] += __uint_as_float(v1.x); d[1][1] += __uint_as_float(v1.y);
                d[1][2] += __uint_as_float(v1.z); d[1][3] += __uint_as_float(v1.w);
                #pragma unroll
                for (int nf = 0; nf < 2; nf++) {
                    int col = jA0 + wn0A + nf * 8 + (l & 3) * 2;
                    #pragma unroll
                    for (int h = 0; h < 2; h++) {
                        int row = rA0 + wr0A + (l >> 2) + h * 8;
                        size_t o = (size_t)row * Hsz + col;
                        float s0 = sigm(d[nf][h * 2]     + atv[nf][h].x);
                        float s1 = sigm(d[nf][h * 2 + 1] + atv[nf][h].y);
                        if (sA == 0) {
                            float2 zz = {s0, s1};
                            *(float2*)(g_Z + o) = zz;
                        } else {
                            __half2 hp;
                            hp.x = __float2half(s0 * hdv[nf][h].x);
                            hp.y = __float2half(s1 * hdv[nf][h].y);
                            *(__half2*)(g_rh_h + o) = hp;
                        }
                    }
                }
            }
            arrive_g(g);
        }

        // ================== phase B for both groups ==========================
        #pragma unroll 1
        for (int pi = 0; pi < 2; pi++) {
            int g = grp[pi];
            wait_g(g, tg[pi]); tg[pi] += 16;
            int rB0 = g * 32;
            stage32_issue(sb + OFF_ACT, g_rh_h, rB0, tid);
            const float* An = g_A + (size_t)2 * TBH + (size_t)t * BH;
            const float* ghn = g_gh + (size_t)(t + 1) * BH;
            bool last = (t == Tsz - 1);
            int col = jB0 + wn0B + (l & 3) * 2;
            float2 anv[2], ghv[2], zv[2], hdv[2];
            if (wid < 8) {
                #pragma unroll
                for (int h = 0; h < 2; h++) {
                    int row = rB0 + wr0B + (l >> 2) + h * 8;
                    size_t o = (size_t)row * Hsz + col;
                    anv[h] = __ldcg((const float2*)(An + o));
                    zv[h]  = __ldcg((const float2*)(g_Z + o));
                    hdv[h] = __ldcg((const float2*)(g_HD + o));
                    if (!last) ghv[h] = __ldcg((const float2*)(ghn + o));
                }
            }
            stage_wait();
            float d[4];
            mma_tile<16>(sb, OFF_WB, kB0, l, wr0B, wn0B, d);
            if (wid >= 8) {
                uint32_t ra = sb + OFF_RED + (uint32_t)(widB * 512 + l * 16);
                uint4 v = {__float_as_uint(d[0]), __float_as_uint(d[1]),
                           __float_as_uint(d[2]), __float_as_uint(d[3])};
                sts16(ra, v);
            }
            __syncthreads();
            if (wid < 8) {
                uint32_t ra = sb + OFF_RED + (uint32_t)(widB * 512 + l * 16);
                uint4 v = *(const uint4*)(smem + (ra - sb));
                d[0] += __uint_as_float(v.x);
                d[1] += __uint_as_float(v.y);
                d[2] += __uint_as_float(v.z);
                d[3] += __uint_as_float(v.w);
                #pragma unroll
                for (int h = 0; h < 2; h++) {
                    int row = rB0 + wr0B + (l >> 2) + h * 8;
                    size_t o = (size_t)row * Hsz + col;
                    #pragma unroll
                    for (int q2 = 0; q2 < 2; q2++) {
                        float ht = tanhf(d[h * 2 + q2] + (q2 ? anv[h].y : anv[h].x));
                        float z  = q2 ? zv[h].y : zv[h].x;
                        float hd = q2 ? hdv[h].y : hdv[h].x;
                        float hp = (1.f - z) * hd + z * ht;
                        if (last) {
                            out[o + q2] = hp;
                        } else {
                            float hdn = (q2 ? ghv[h].y : ghv[h].x) * hp;
                            g_HD[o + q2] = hdn;
                            g_hd_h[o + q2] = __float2half(hdn);
                        }
                    }
                }
            }
            arrive_g(g);
        }
    }
}

// ---------------- launch ----------------
extern "C" void kernel_launch(void* const* d_in, const int* in_sizes, int n_in,
                              void* d_out, int out_size) {
    const float* x    = (const float*)d_in[0];
    const float* xl   = (const float*)d_in[1];
    const float* mk   = (const float*)d_in[2];
    const float* dl   = (const float*)d_in[3];
    const float* xm   = (const float*)d_in[4];
    const float* Wz   = (const float*)d_in[5];
    const float* bz   = (const float*)d_in[6];
    const float* Wr   = (const float*)d_in[7];
    const float* br   = (const float*)d_in[8];
    const float* Wn   = (const float*)d_in[9];
    const float* bn   = (const float*)d_in[10];
    const float* Wgx  = (const float*)d_in[11];
    const float* bgx  = (const float*)d_in[12];
    const float* Wgh  = (const float*)d_in[13];
    const float* bgh  = (const float*)d_in[14];

    static int smem_set = 0;
    if (!smem_set) {
        cudaFuncSetAttribute(loop_kernel,
                             cudaFuncAttributeMaxDynamicSharedMemorySize, SMEM_TOTAL);
        cudaFuncSetAttribute(p12_kernel,
                             cudaFuncAttributeMaxDynamicSharedMemorySize, PG_SMEM);
        smem_set = 1;
    }

    p0prep_kernel<<<65536 + 4864 + 1, 256>>>(x, xl, mk, dl, xm, Wgx, bgx,
                                             Wz, Wr, Wn, Wgh);
    p12_kernel<<<dim3(16, 1024), 256, PG_SMEM>>>(bz, br, bn, bgh);
    dummy_kernel<<<1, 32>>>();
    loop_kernel<<<NCTA, 512, SMEM_TOTAL>>>((float*)d_out);
}